// round 3
// baseline (speedup 1.0000x reference)
#include <cuda_runtime.h>
#include <math.h>

#define NTOK 2304
#define HWDIM 48
#define FEATC 256
#define NHEAD 8
#define DKV 32

typedef unsigned long long ull;

// Scratch: pe(30*2304) + biasQ/biasK(2*256*2304) + Q,K,V,O,O2,H1,PRE (7*4*256*2304)
__device__ float g_scratch[17763840];
__device__ float g_scale[256];
__device__ float g_shift[256];

// ---- f32x2 helpers ----
__device__ __forceinline__ ull pk(float lo, float hi) {
    ull r; asm("mov.b64 %0,{%1,%2};" : "=l"(r) : "f"(lo), "f"(hi)); return r;
}
__device__ __forceinline__ void fma2(ull& d, ull a, ull b) {
    asm("fma.rn.f32x2 %0,%1,%2,%0;" : "+l"(d) : "l"(a), "l"(b));
}
__device__ __forceinline__ float plo(ull u) { return __uint_as_float((unsigned)u); }
__device__ __forceinline__ float phi(ull u) { return __uint_as_float((unsigned)(u >> 32)); }

// ---------------- PE ----------------
__global__ void pe_kernel(float* __restrict__ pe) {
    int idx = blockIdx.x * blockDim.x + threadIdx.x;
    if (idx >= 30 * NTOK) return;
    int c = idx / NTOK, p = idx % NTOK;
    int i = p / HWDIM, j = p % HWDIM;
    const float SC = 6.283185307179586f;
    int axis = c / 10, t = c % 10;
    float e;
    if (axis == 0)      e = (float)(i + 1) / (HWDIM + 1e-6f) * SC;
    else if (axis == 1) e = (float)(j + 1) / (HWDIM + 1e-6f) * SC;
    else                e = SC;
    float freq = powf(10000.0f, (2.0f * (float)(t >> 1)) / 10.0f);
    float ph = e / freq;
    pe[idx] = (t & 1) ? cosf(ph) : sinf(ph);
}

// ---------------- PE bias ----------------
__global__ void pebias_kernel(const float* __restrict__ pe,
                              const float* __restrict__ wq,
                              const float* __restrict__ wk,
                              float* __restrict__ bq,
                              float* __restrict__ bk) {
    int p = blockIdx.x * blockDim.x + threadIdx.x;
    int c = blockIdx.y;
    const float* w = (blockIdx.z == 0 ? wq : wk) + (size_t)c * 286 + 256;
    float* o = (blockIdx.z == 0 ? bq : bk);
    float s = 0.f;
#pragma unroll
    for (int j = 0; j < 30; j++) s += w[j] * pe[j * NTOK + p];
    o[(size_t)c * NTOK + p] = s;
}

// ---------------- SGEMM body: out[256 x 2304] = W @ X + epilogue ----------------
__device__ __forceinline__ void gemm_body(const float* __restrict__ W, int ldw,
                                          const float* __restrict__ X,
                                          const float* __restrict__ bMat,
                                          const float* __restrict__ bVec,
                                          const float* __restrict__ resid,
                                          float* __restrict__ out, int relu) {
    __shared__ float As[16][68];
    __shared__ float Bs[16][64];
    int tid = threadIdx.x;
    int ty = tid >> 4, tx = tid & 15;
    int row0 = blockIdx.y * 64, col0 = blockIdx.x * 64;
    float acc[4][4];
#pragma unroll
    for (int i = 0; i < 4; i++)
#pragma unroll
        for (int j = 0; j < 4; j++) acc[i][j] = 0.f;

    for (int k0 = 0; k0 < 256; k0 += 16) {
#pragma unroll
        for (int i = 0; i < 4; i++) {
            int idx = tid + i * 256;
            int kk = idx & 15, mm = idx >> 4;
            As[kk][mm] = W[(size_t)(row0 + mm) * ldw + k0 + kk];
        }
#pragma unroll
        for (int i = 0; i < 4; i++) {
            int idx = tid + i * 256;
            int nn = idx & 63, kk = idx >> 6;
            Bs[kk][nn] = X[(size_t)(k0 + kk) * NTOK + col0 + nn];
        }
        __syncthreads();
#pragma unroll
        for (int kk = 0; kk < 16; kk++) {
            float4 a4 = *(const float4*)&As[kk][ty * 4];
            float4 b4 = *(const float4*)&Bs[kk][tx * 4];
            float a[4] = {a4.x, a4.y, a4.z, a4.w};
            float b[4] = {b4.x, b4.y, b4.z, b4.w};
#pragma unroll
            for (int i = 0; i < 4; i++)
#pragma unroll
                for (int j = 0; j < 4; j++) acc[i][j] += a[i] * b[j];
        }
        __syncthreads();
    }

#pragma unroll
    for (int i = 0; i < 4; i++) {
        int r = row0 + ty * 4 + i;
#pragma unroll
        for (int j = 0; j < 4; j++) {
            int c = col0 + tx * 4 + j;
            size_t o = (size_t)r * NTOK + c;
            float v = acc[i][j];
            if (bMat)  v += bMat[o];
            if (bVec)  v += bVec[r];
            if (relu)  v = fmaxf(v, 0.f);
            if (resid) v += resid[o];
            out[o] = v;
        }
    }
}

// Fused QKV projections: z = batch*3 + op
__global__ void proj_kernel(const float* __restrict__ wq, const float* __restrict__ wk,
                            const float* __restrict__ wv,
                            const float* __restrict__ q, const float* __restrict__ k,
                            const float* __restrict__ v,
                            const float* __restrict__ bq, const float* __restrict__ bk,
                            float* __restrict__ Q, float* __restrict__ K, float* __restrict__ V) {
    int z = blockIdx.z;
    int b = z / 3, op = z - 3 * b;
    size_t off = (size_t)b * FEATC * NTOK;
    const float* W;
    const float* X;
    const float* bMat;
    float* out;
    int ldw;
    if (op == 0)      { W = wq; ldw = 286; X = q + off; bMat = bq; out = Q + off; }
    else if (op == 1) { W = wk; ldw = 286; X = k + off; bMat = bk; out = K + off; }
    else              { W = wv; ldw = 256; X = v + off; bMat = nullptr; out = V + off; }
    gemm_body(W, ldw, X, bMat, nullptr, nullptr, out, 0);
}

// Batched generic GEMM: z = batch
__global__ void gemm_kernel(const float* __restrict__ W, int ldw,
                            const float* __restrict__ X,
                            const float* __restrict__ bVec,
                            const float* __restrict__ resid,
                            float* __restrict__ out, int relu) {
    size_t off = (size_t)blockIdx.z * FEATC * NTOK;
    gemm_body(W, ldw, X + off, nullptr, bVec, resid ? resid + off : nullptr, out + off, relu);
}

// ---------------- Attention: no-max softmax (scores provably tiny), f32x2, 1 query/thread ----------------
__global__ void __launch_bounds__(128) attn_kernel(const float* __restrict__ Q,
                                                   const float* __restrict__ K,
                                                   const float* __restrict__ V,
                                                   float* __restrict__ O) {
    int bh = blockIdx.y;
    int b = bh >> 3, h = bh & 7;
    size_t head_off = ((size_t)b * FEATC + h * DKV) * NTOK;
    const float* Qp = Q + head_off;
    const float* Kp = K + head_off;
    const float* Vp = V + head_off;
    float* Op = O + head_off;

    int qi = blockIdx.x * 128 + threadIdx.x;

    const float sc = 0.17677669529663687f;  // 1/sqrt(32)
    ull qp[16];
#pragma unroll
    for (int d2 = 0; d2 < 16; d2++)
        qp[d2] = pk(Qp[(size_t)(2 * d2) * NTOK + qi] * sc,
                    Qp[(size_t)(2 * d2 + 1) * NTOK + qi] * sc);

    float l = 0.f;
    ull acc[16];
#pragma unroll
    for (int d2 = 0; d2 < 16; d2++) acc[d2] = 0ull;

    __shared__ float Ks[64][36];
    __shared__ float Vs[64][36];

    for (int kb = 0; kb < NTOK; kb += 64) {
        __syncthreads();
#pragma unroll
        for (int i = 0; i < 16; i++) {
            int idx = threadIdx.x + i * 128;
            int d = idx >> 6, j = idx & 63;
            Ks[j][d] = Kp[(size_t)d * NTOK + kb + j];
            Vs[j][d] = Vp[(size_t)d * NTOK + kb + j];
        }
        __syncthreads();

#pragma unroll 1
        for (int c0 = 0; c0 < 64; c0 += 8) {
            float p[8];
#pragma unroll
            for (int jj = 0; jj < 8; jj++) {
                const ulonglong2* kr = (const ulonglong2*)&Ks[c0 + jj][0];
                ull sp = 0ull;
#pragma unroll
                for (int i = 0; i < 8; i++) {
                    ulonglong2 kk = kr[i];
                    fma2(sp, qp[2 * i], kk.x);
                    fma2(sp, qp[2 * i + 1], kk.y);
                }
                p[jj] = __expf(plo(sp) + phi(sp));
            }
#pragma unroll
            for (int jj = 0; jj < 8; jj++) {
                l += p[jj];
                ull pd = pk(p[jj], p[jj]);
                const ulonglong2* vr = (const ulonglong2*)&Vs[c0 + jj][0];
#pragma unroll
                for (int i = 0; i < 8; i++) {
                    ulonglong2 vv = vr[i];
                    fma2(acc[2 * i], pd, vv.x);
                    fma2(acc[2 * i + 1], pd, vv.y);
                }
            }
        }
    }
    float inv = 1.f / l;
#pragma unroll
    for (int d2 = 0; d2 < 16; d2++) {
        Op[(size_t)(2 * d2) * NTOK + qi]     = plo(acc[d2]) * inv;
        Op[(size_t)(2 * d2 + 1) * NTOK + qi] = phi(acc[d2]) * inv;
    }
}

// ---------------- BN ----------------
__global__ void bnstats_kernel(const float* __restrict__ pre,
                               const float* __restrict__ gamma,
                               const float* __restrict__ beta) {
    int c = blockIdx.x;
    float s = 0.f, s2 = 0.f;
    for (int b = 0; b < 4; b++) {
        const float* p = pre + ((size_t)b * FEATC + c) * NTOK;
        for (int i = threadIdx.x; i < NTOK; i += 256) {
            float v = p[i];
            s += v;
            s2 += v * v;
        }
    }
    __shared__ float sh0[256], sh1[256];
    sh0[threadIdx.x] = s;
    sh1[threadIdx.x] = s2;
    __syncthreads();
    for (int st = 128; st > 0; st >>= 1) {
        if (threadIdx.x < st) {
            sh0[threadIdx.x] += sh0[threadIdx.x + st];
            sh1[threadIdx.x] += sh1[threadIdx.x + st];
        }
        __syncthreads();
    }
    if (threadIdx.x == 0) {
        const float n = 4.0f * NTOK;
        float mean = sh0[0] / n;
        float var = sh1[0] / n - mean * mean;
        float is = rsqrtf(var + 1e-5f);
        float scl = gamma[c] * is;
        g_scale[c] = scl;
        g_shift[c] = beta[c] - mean * scl;
    }
}

__global__ void bnapply_kernel(const float* __restrict__ pre, float* __restrict__ out) {
    int idx = blockIdx.x * 256 + threadIdx.x;
    if (idx >= 4 * FEATC * NTOK) return;
    int c = (idx / NTOK) & 255;
    out[idx] = pre[idx] * g_scale[c] + g_shift[c];
}

// ---------------- launch ----------------
extern "C" void kernel_launch(void* const* d_in, const int* in_sizes, int n_in,
                              void* d_out, int out_size) {
    const float* q     = (const float*)d_in[0];
    const float* k     = (const float*)d_in[1];
    const float* v     = (const float*)d_in[2];
    const float* wq    = (const float*)d_in[3];
    const float* wk    = (const float*)d_in[4];
    const float* wv    = (const float*)d_in[5];
    const float* wfc   = (const float*)d_in[6];
    const float* w1    = (const float*)d_in[7];
    const float* b1    = (const float*)d_in[8];
    const float* w2    = (const float*)d_in[9];
    const float* b2    = (const float*)d_in[10];
    const float* gamma = (const float*)d_in[11];
    const float* beta  = (const float*)d_in[12];
    float* out = (float*)d_out;

    float* base = nullptr;
    cudaGetSymbolAddress((void**)&base, g_scratch);
    float* pe  = base;
    float* bq  = base + 69120;
    float* bk  = bq + 589824;
    float* Q   = bk + 589824;
    float* K   = Q + 2359296;
    float* V   = K + 2359296;
    float* O   = V + 2359296;
    float* O2  = O + 2359296;
    float* H1  = O2 + 2359296;
    float* PRE = H1 + 2359296;

    pe_kernel<<<(30 * NTOK + 255) / 256, 256>>>(pe);
    {
        dim3 g(NTOK / 128, 256, 2);
        pebias_kernel<<<g, 128>>>(pe, wq, wk, bq, bk);
    }
    {
        dim3 g(NTOK / 64, FEATC / 64, 12);
        proj_kernel<<<g, 256>>>(wq, wk, wv, q, k, v, bq, bk, Q, K, V);
    }
    {
        dim3 ga(NTOK / 128, 32);
        attn_kernel<<<ga, 128>>>(Q, K, V, O);
    }
    dim3 gg(NTOK / 64, FEATC / 64, 4);
    gemm_kernel<<<gg, 256>>>(wfc, 256, O, nullptr, nullptr, O2, 0);
    gemm_kernel<<<gg, 256>>>(w1, 256, O2, b1, nullptr, H1, 1);
    gemm_kernel<<<gg, 256>>>(w2, 256, H1, b2, O2, PRE, 0);
    bnstats_kernel<<<256, 256>>>(PRE, gamma, beta);
    bnapply_kernel<<<(4 * FEATC * NTOK + 255) / 256, 256>>>(PRE, out);
}

// round 4
// speedup vs baseline: 1.1843x; 1.1843x over previous
#include <cuda_runtime.h>
#include <math.h>

#define NTOK 2304
#define HWDIM 48
#define FEATC 256
#define NHEAD 8
#define DKV 32
#define NSPLIT 4
#define KSEG (NTOK / NSPLIT)   // 576

typedef unsigned long long ull;

// Scratch: pe + biasQ/K + Q,K,V,O,O2,H1,PRE + attention partials
__device__ float g_scratch[27495936];
__device__ float g_scale[256];
__device__ float g_shift[256];

// ---- f32x2 helpers ----
__device__ __forceinline__ ull pk(float lo, float hi) {
    ull r; asm("mov.b64 %0,{%1,%2};" : "=l"(r) : "f"(lo), "f"(hi)); return r;
}
__device__ __forceinline__ void fma2(ull& d, ull a, ull b) {
    asm("fma.rn.f32x2 %0,%1,%2,%0;" : "+l"(d) : "l"(a), "l"(b));
}
__device__ __forceinline__ float plo(ull u) { return __uint_as_float((unsigned)u); }
__device__ __forceinline__ float phi(ull u) { return __uint_as_float((unsigned)(u >> 32)); }

// ---------------- PE ----------------
__global__ void pe_kernel(float* __restrict__ pe) {
    int idx = blockIdx.x * blockDim.x + threadIdx.x;
    if (idx >= 30 * NTOK) return;
    int c = idx / NTOK, p = idx % NTOK;
    int i = p / HWDIM, j = p % HWDIM;
    const float SC = 6.283185307179586f;
    int axis = c / 10, t = c % 10;
    float e;
    if (axis == 0)      e = (float)(i + 1) / (HWDIM + 1e-6f) * SC;
    else if (axis == 1) e = (float)(j + 1) / (HWDIM + 1e-6f) * SC;
    else                e = SC;
    float freq = powf(10000.0f, (2.0f * (float)(t >> 1)) / 10.0f);
    float ph = e / freq;
    pe[idx] = (t & 1) ? cosf(ph) : sinf(ph);
}

// ---------------- PE bias ----------------
__global__ void pebias_kernel(const float* __restrict__ pe,
                              const float* __restrict__ wq,
                              const float* __restrict__ wk,
                              float* __restrict__ bq,
                              float* __restrict__ bk) {
    int p = blockIdx.x * blockDim.x + threadIdx.x;
    int c = blockIdx.y;
    const float* w = (blockIdx.z == 0 ? wq : wk) + (size_t)c * 286 + 256;
    float* o = (blockIdx.z == 0 ? bq : bk);
    float s = 0.f;
#pragma unroll
    for (int j = 0; j < 30; j++) s += w[j] * pe[j * NTOK + p];
    o[(size_t)c * NTOK + p] = s;
}

// ---------------- SGEMM body ----------------
__device__ __forceinline__ void gemm_body(const float* __restrict__ W, int ldw,
                                          const float* __restrict__ X,
                                          const float* __restrict__ bMat,
                                          const float* __restrict__ bVec,
                                          const float* __restrict__ resid,
                                          float* __restrict__ out, int relu) {
    __shared__ float As[16][68];
    __shared__ float Bs[16][64];
    int tid = threadIdx.x;
    int ty = tid >> 4, tx = tid & 15;
    int row0 = blockIdx.y * 64, col0 = blockIdx.x * 64;
    float acc[4][4];
#pragma unroll
    for (int i = 0; i < 4; i++)
#pragma unroll
        for (int j = 0; j < 4; j++) acc[i][j] = 0.f;

    for (int k0 = 0; k0 < 256; k0 += 16) {
#pragma unroll
        for (int i = 0; i < 4; i++) {
            int idx = tid + i * 256;
            int kk = idx & 15, mm = idx >> 4;
            As[kk][mm] = W[(size_t)(row0 + mm) * ldw + k0 + kk];
        }
#pragma unroll
        for (int i = 0; i < 4; i++) {
            int idx = tid + i * 256;
            int nn = idx & 63, kk = idx >> 6;
            Bs[kk][nn] = X[(size_t)(k0 + kk) * NTOK + col0 + nn];
        }
        __syncthreads();
#pragma unroll
        for (int kk = 0; kk < 16; kk++) {
            float4 a4 = *(const float4*)&As[kk][ty * 4];
            float4 b4 = *(const float4*)&Bs[kk][tx * 4];
            float a[4] = {a4.x, a4.y, a4.z, a4.w};
            float b[4] = {b4.x, b4.y, b4.z, b4.w};
#pragma unroll
            for (int i = 0; i < 4; i++)
#pragma unroll
                for (int j = 0; j < 4; j++) acc[i][j] += a[i] * b[j];
        }
        __syncthreads();
    }

#pragma unroll
    for (int i = 0; i < 4; i++) {
        int r = row0 + ty * 4 + i;
#pragma unroll
        for (int j = 0; j < 4; j++) {
            int c = col0 + tx * 4 + j;
            size_t o = (size_t)r * NTOK + c;
            float v = acc[i][j];
            if (bMat)  v += bMat[o];
            if (bVec)  v += bVec[r];
            if (relu)  v = fmaxf(v, 0.f);
            if (resid) v += resid[o];
            out[o] = v;
        }
    }
}

// Fused QKV projections: z = batch*3 + op
__global__ void proj_kernel(const float* __restrict__ wq, const float* __restrict__ wk,
                            const float* __restrict__ wv,
                            const float* __restrict__ q, const float* __restrict__ k,
                            const float* __restrict__ v,
                            const float* __restrict__ bq, const float* __restrict__ bk,
                            float* __restrict__ Q, float* __restrict__ K, float* __restrict__ V) {
    int z = blockIdx.z;
    int b = z / 3, op = z - 3 * b;
    size_t off = (size_t)b * FEATC * NTOK;
    const float* W;
    const float* X;
    const float* bMat;
    float* out;
    int ldw;
    if (op == 0)      { W = wq; ldw = 286; X = q + off; bMat = bq; out = Q + off; }
    else if (op == 1) { W = wk; ldw = 286; X = k + off; bMat = bk; out = K + off; }
    else              { W = wv; ldw = 256; X = v + off; bMat = nullptr; out = V + off; }
    gemm_body(W, ldw, X, bMat, nullptr, nullptr, out, 0);
}

// Batched generic GEMM: z = batch
__global__ void gemm_kernel(const float* __restrict__ W, int ldw,
                            const float* __restrict__ X,
                            const float* __restrict__ bVec,
                            const float* __restrict__ resid,
                            float* __restrict__ out, int relu) {
    size_t off = (size_t)blockIdx.z * FEATC * NTOK;
    gemm_body(W, ldw, X + off, nullptr, bVec, resid ? resid + off : nullptr, out + off, relu);
}

// ---------------- Attention: no-max softmax, f32x2, 2 queries/thread, split keys ----------------
// Partials: Pacc[bh][split][d][q], Lp[bh][split][q]
__global__ void __launch_bounds__(128, 3) attn_kernel(const float* __restrict__ Q,
                                                      const float* __restrict__ K,
                                                      const float* __restrict__ V,
                                                      float* __restrict__ Pacc,
                                                      float* __restrict__ Lp) {
    int bh = blockIdx.y;
    int s = blockIdx.z;
    size_t head_off = (size_t)bh * DKV * NTOK;
    const float* Qp = Q + head_off;
    const float* Kp = K + head_off;
    const float* Vp = V + head_off;
    float* Pp = Pacc + (size_t)(bh * NSPLIT + s) * DKV * NTOK;
    float* Lq = Lp + (size_t)(bh * NSPLIT + s) * NTOK;

    int q0 = blockIdx.x * 256 + threadIdx.x;
    int q1 = q0 + 128;

    const float sc = 0.17677669529663687f;  // 1/sqrt(32)
    ull qp0[16], qp1[16];
#pragma unroll
    for (int d2 = 0; d2 < 16; d2++) {
        qp0[d2] = pk(Qp[(2 * d2) * NTOK + q0] * sc, Qp[(2 * d2 + 1) * NTOK + q0] * sc);
        qp1[d2] = pk(Qp[(2 * d2) * NTOK + q1] * sc, Qp[(2 * d2 + 1) * NTOK + q1] * sc);
    }

    float l0 = 0.f, l1 = 0.f;
    ull acc0[16], acc1[16];
#pragma unroll
    for (int d2 = 0; d2 < 16; d2++) { acc0[d2] = 0ull; acc1[d2] = 0ull; }

    __shared__ float Ks[64][36];
    __shared__ float Vs[64][36];

    int kend = s * KSEG + KSEG;
    for (int kb = s * KSEG; kb < kend; kb += 64) {
        __syncthreads();
#pragma unroll
        for (int i = 0; i < 16; i++) {
            int idx = threadIdx.x + i * 128;
            int d = idx >> 6, j = idx & 63;
            Ks[j][d] = Kp[d * NTOK + kb + j];
            Vs[j][d] = Vp[d * NTOK + kb + j];
        }
        __syncthreads();

#pragma unroll 1
        for (int c0 = 0; c0 < 64; c0 += 8) {
            float p0[8], p1[8];
#pragma unroll
            for (int jj = 0; jj < 8; jj++) {
                const ulonglong2* kr = (const ulonglong2*)&Ks[c0 + jj][0];
                ull sp0 = 0ull, sp1 = 0ull;
#pragma unroll
                for (int i = 0; i < 8; i++) {
                    ulonglong2 kk = kr[i];
                    fma2(sp0, qp0[2 * i], kk.x);
                    fma2(sp0, qp0[2 * i + 1], kk.y);
                    fma2(sp1, qp1[2 * i], kk.x);
                    fma2(sp1, qp1[2 * i + 1], kk.y);
                }
                p0[jj] = __expf(plo(sp0) + phi(sp0));
                p1[jj] = __expf(plo(sp1) + phi(sp1));
            }
#pragma unroll
            for (int jj = 0; jj < 8; jj++) {
                l0 += p0[jj];
                l1 += p1[jj];
                ull pd0 = pk(p0[jj], p0[jj]);
                ull pd1 = pk(p1[jj], p1[jj]);
                const ulonglong2* vr = (const ulonglong2*)&Vs[c0 + jj][0];
#pragma unroll
                for (int i = 0; i < 8; i++) {
                    ulonglong2 vv = vr[i];
                    fma2(acc0[2 * i], pd0, vv.x);
                    fma2(acc0[2 * i + 1], pd0, vv.y);
                    fma2(acc1[2 * i], pd1, vv.x);
                    fma2(acc1[2 * i + 1], pd1, vv.y);
                }
            }
        }
    }
#pragma unroll
    for (int d2 = 0; d2 < 16; d2++) {
        Pp[(2 * d2) * NTOK + q0]     = plo(acc0[d2]);
        Pp[(2 * d2 + 1) * NTOK + q0] = phi(acc0[d2]);
        Pp[(2 * d2) * NTOK + q1]     = plo(acc1[d2]);
        Pp[(2 * d2 + 1) * NTOK + q1] = phi(acc1[d2]);
    }
    Lq[q0] = l0;
    Lq[q1] = l1;
}

// Combine split partials -> O[bh*32+d][q]
__global__ void attn_combine_kernel(const float* __restrict__ Pacc,
                                    const float* __restrict__ Lp,
                                    float* __restrict__ O) {
    int idx = blockIdx.x * 256 + threadIdx.x;
    if (idx >= 32 * DKV * NTOK) return;
    int q = idx % NTOK;
    int c = idx / NTOK;          // bh*32 + d
    int bh = c >> 5, d = c & 31;
    size_t pbase = ((size_t)bh * NSPLIT * DKV + d) * NTOK + q;
    size_t lbase = (size_t)bh * NSPLIT * NTOK + q;
    float a = 0.f, l = 0.f;
#pragma unroll
    for (int s = 0; s < NSPLIT; s++) {
        a += Pacc[pbase + (size_t)s * DKV * NTOK];
        l += Lp[lbase + (size_t)s * NTOK];
    }
    O[idx] = a / l;
}

// ---------------- BN ----------------
__global__ void bnstats_kernel(const float* __restrict__ pre,
                               const float* __restrict__ gamma,
                               const float* __restrict__ beta) {
    int c = blockIdx.x;
    float s = 0.f, s2 = 0.f;
    for (int b = 0; b < 4; b++) {
        const float* p = pre + ((size_t)b * FEATC + c) * NTOK;
        for (int i = threadIdx.x; i < NTOK; i += 256) {
            float v = p[i];
            s += v;
            s2 += v * v;
        }
    }
    __shared__ float sh0[256], sh1[256];
    sh0[threadIdx.x] = s;
    sh1[threadIdx.x] = s2;
    __syncthreads();
    for (int st = 128; st > 0; st >>= 1) {
        if (threadIdx.x < st) {
            sh0[threadIdx.x] += sh0[threadIdx.x + st];
            sh1[threadIdx.x] += sh1[threadIdx.x + st];
        }
        __syncthreads();
    }
    if (threadIdx.x == 0) {
        const float n = 4.0f * NTOK;
        float mean = sh0[0] / n;
        float var = sh1[0] / n - mean * mean;
        float is = rsqrtf(var + 1e-5f);
        float scl = gamma[c] * is;
        g_scale[c] = scl;
        g_shift[c] = beta[c] - mean * scl;
    }
}

__global__ void bnapply_kernel(const float* __restrict__ pre, float* __restrict__ out) {
    int idx = blockIdx.x * 256 + threadIdx.x;
    if (idx >= 4 * FEATC * NTOK) return;
    int c = (idx / NTOK) & 255;
    out[idx] = pre[idx] * g_scale[c] + g_shift[c];
}

// ---------------- launch ----------------
extern "C" void kernel_launch(void* const* d_in, const int* in_sizes, int n_in,
                              void* d_out, int out_size) {
    const float* q     = (const float*)d_in[0];
    const float* k     = (const float*)d_in[1];
    const float* v     = (const float*)d_in[2];
    const float* wq    = (const float*)d_in[3];
    const float* wk    = (const float*)d_in[4];
    const float* wv    = (const float*)d_in[5];
    const float* wfc   = (const float*)d_in[6];
    const float* w1    = (const float*)d_in[7];
    const float* b1    = (const float*)d_in[8];
    const float* w2    = (const float*)d_in[9];
    const float* b2    = (const float*)d_in[10];
    const float* gamma = (const float*)d_in[11];
    const float* beta  = (const float*)d_in[12];
    float* out = (float*)d_out;

    float* base = nullptr;
    cudaGetSymbolAddress((void**)&base, g_scratch);
    float* pe   = base;
    float* bq   = base + 69120;
    float* bk   = bq + 589824;
    float* Q    = bk + 589824;
    float* K    = Q + 2359296;
    float* V    = K + 2359296;
    float* O    = V + 2359296;
    float* O2   = O + 2359296;
    float* H1   = O2 + 2359296;
    float* PRE  = H1 + 2359296;
    float* Pacc = PRE + 2359296;   // 9437184
    float* Lpar = Pacc + 9437184;  // 294912

    pe_kernel<<<(30 * NTOK + 255) / 256, 256>>>(pe);
    {
        dim3 g(NTOK / 128, 256, 2);
        pebias_kernel<<<g, 128>>>(pe, wq, wk, bq, bk);
    }
    {
        dim3 g(NTOK / 64, FEATC / 64, 12);
        proj_kernel<<<g, 256>>>(wq, wk, wv, q, k, v, bq, bk, Q, K, V);
    }
    {
        dim3 ga(NTOK / 256, 32, NSPLIT);
        attn_kernel<<<ga, 128>>>(Q, K, V, Pacc, Lpar);
        attn_combine_kernel<<<(32 * DKV * NTOK + 255) / 256, 256>>>(Pacc, Lpar, O);
    }
    dim3 gg(NTOK / 64, FEATC / 64, 4);
    gemm_kernel<<<gg, 256>>>(wfc, 256, O, nullptr, nullptr, O2, 0);
    gemm_kernel<<<gg, 256>>>(w1, 256, O2, b1, nullptr, H1, 1);
    gemm_kernel<<<gg, 256>>>(w2, 256, H1, b2, O2, PRE, 0);
    bnstats_kernel<<<256, 256>>>(PRE, gamma, beta);
    bnapply_kernel<<<(4 * FEATC * NTOK + 255) / 256, 256>>>(PRE, out);
}

// round 6
// speedup vs baseline: 4.5677x; 3.8570x over previous
#include <cuda_runtime.h>
#include <cuda_fp16.h>
#include <math.h>

#define NTOK 2304
#define HWDIM 48
#define FEATC 256
#define NHEAD 8
#define DKV 32
#define NKT 36   // key tiles of 64
#define NQT 18   // query tiles of 128

typedef unsigned long long ull;
typedef unsigned int u32;

__device__ float g_scratch[17763840];
__device__ float g_scale[256];
__device__ float g_shift[256];

// ---- helpers ----
__device__ __forceinline__ u32 f16pack(float lo, float hi) {
    u32 r;
    asm("cvt.rn.f16x2.f32 %0, %1, %2;" : "=r"(r) : "f"(hi), "f"(lo));
    return r;
}
__device__ __forceinline__ void mma16816(float* d, u32 a0, u32 a1, u32 a2, u32 a3,
                                         u32 b0, u32 b1) {
    asm volatile(
        "mma.sync.aligned.m16n8k16.row.col.f32.f16.f16.f32 "
        "{%0,%1,%2,%3},{%4,%5,%6,%7},{%8,%9},{%0,%1,%2,%3};"
        : "+f"(d[0]), "+f"(d[1]), "+f"(d[2]), "+f"(d[3])
        : "r"(a0), "r"(a1), "r"(a2), "r"(a3), "r"(b0), "r"(b1));
}

// ================= PE =================
__global__ void pe_kernel(float* __restrict__ pe) {
    int idx = blockIdx.x * blockDim.x + threadIdx.x;
    if (idx >= 30 * NTOK) return;
    int c = idx / NTOK, p = idx % NTOK;
    int i = p / HWDIM, j = p % HWDIM;
    const float SC = 6.283185307179586f;
    int axis = c / 10, t = c % 10;
    float e;
    if (axis == 0)      e = (float)(i + 1) / (HWDIM + 1e-6f) * SC;
    else if (axis == 1) e = (float)(j + 1) / (HWDIM + 1e-6f) * SC;
    else                e = SC;
    float freq = powf(10000.0f, (2.0f * (float)(t >> 1)) / 10.0f);
    float ph = e / freq;
    pe[idx] = (t & 1) ? cosf(ph) : sinf(ph);
}

__global__ void pebias_kernel(const float* __restrict__ pe,
                              const float* __restrict__ wq,
                              const float* __restrict__ wk,
                              float* __restrict__ bq,
                              float* __restrict__ bk) {
    int p = blockIdx.x * blockDim.x + threadIdx.x;
    int c = blockIdx.y;
    const float* w = (blockIdx.z == 0 ? wq : wk) + (size_t)c * 286 + 256;
    float* o = (blockIdx.z == 0 ? bq : bk);
    float s = 0.f;
#pragma unroll
    for (int j = 0; j < 30; j++) s += w[j] * pe[j * NTOK + p];
    o[(size_t)c * NTOK + p] = s;
}

// ================= SGEMM (fp32) =================
__device__ __forceinline__ void gemm_body(const float* __restrict__ W, int ldw,
                                          const float* __restrict__ X,
                                          const float* __restrict__ bVec,
                                          const float* __restrict__ resid,
                                          float* __restrict__ out, int relu) {
    __shared__ float As[16][68];
    __shared__ float Bs[16][64];
    int tid = threadIdx.x;
    int ty = tid >> 4, tx = tid & 15;
    int row0 = blockIdx.y * 64, col0 = blockIdx.x * 64;
    float acc[4][4];
#pragma unroll
    for (int i = 0; i < 4; i++)
#pragma unroll
        for (int j = 0; j < 4; j++) acc[i][j] = 0.f;

    for (int k0 = 0; k0 < 256; k0 += 16) {
#pragma unroll
        for (int i = 0; i < 4; i++) {
            int idx = tid + i * 256;
            int kk = idx & 15, mm = idx >> 4;
            As[kk][mm] = W[(size_t)(row0 + mm) * ldw + k0 + kk];
        }
#pragma unroll
        for (int i = 0; i < 4; i++) {
            int idx = tid + i * 256;
            int nn = idx & 63, kk = idx >> 6;
            Bs[kk][nn] = X[(size_t)(k0 + kk) * NTOK + col0 + nn];
        }
        __syncthreads();
#pragma unroll
        for (int kk = 0; kk < 16; kk++) {
            float4 a4 = *(const float4*)&As[kk][ty * 4];
            float4 b4 = *(const float4*)&Bs[kk][tx * 4];
            float a[4] = {a4.x, a4.y, a4.z, a4.w};
            float b[4] = {b4.x, b4.y, b4.z, b4.w};
#pragma unroll
            for (int i = 0; i < 4; i++)
#pragma unroll
                for (int j = 0; j < 4; j++) acc[i][j] += a[i] * b[j];
        }
        __syncthreads();
    }
#pragma unroll
    for (int i = 0; i < 4; i++) {
        int r = row0 + ty * 4 + i;
#pragma unroll
        for (int j = 0; j < 4; j++) {
            int c = col0 + tx * 4 + j;
            size_t o = (size_t)r * NTOK + c;
            float v = acc[i][j];
            if (bVec)  v += bVec[r];
            if (relu)  v = fmaxf(v, 0.f);
            if (resid) v += resid[o];
            out[o] = v;
        }
    }
}

// ================= QKV projection -> fp16 =================
// Qh/Kh: [bh][token][32] token-major (Q pre-scaled by 1/sqrt(32)); Vh: [bh*32+d][token].
__global__ void proj_kernel(const float* __restrict__ wq, const float* __restrict__ wk,
                            const float* __restrict__ wv,
                            const float* __restrict__ q, const float* __restrict__ k,
                            const float* __restrict__ v,
                            const float* __restrict__ bq, const float* __restrict__ bk,
                            __half* __restrict__ Qh, __half* __restrict__ Kh,
                            __half* __restrict__ Vh) {
    int z = blockIdx.z;
    int b = z / 3, op = z - 3 * b;
    size_t off = (size_t)b * FEATC * NTOK;
    const float* W;
    const float* X;
    const float* bMat;
    int ldw;
    if (op == 0)      { W = wq; ldw = 286; X = q + off; bMat = bq; }
    else if (op == 1) { W = wk; ldw = 286; X = k + off; bMat = bk; }
    else              { W = wv; ldw = 256; X = v + off; bMat = nullptr; }

    __shared__ float As[16][68];
    __shared__ float Bs[16][64];
    int tid = threadIdx.x;
    int ty = tid >> 4, tx = tid & 15;
    int row0 = blockIdx.y * 64, col0 = blockIdx.x * 64;
    float acc[4][4];
#pragma unroll
    for (int i = 0; i < 4; i++)
#pragma unroll
        for (int j = 0; j < 4; j++) acc[i][j] = 0.f;

    for (int k0 = 0; k0 < 256; k0 += 16) {
#pragma unroll
        for (int i = 0; i < 4; i++) {
            int idx = tid + i * 256;
            int kk = idx & 15, mm = idx >> 4;
            As[kk][mm] = W[(size_t)(row0 + mm) * ldw + k0 + kk];
        }
#pragma unroll
        for (int i = 0; i < 4; i++) {
            int idx = tid + i * 256;
            int nn = idx & 63, kk = idx >> 6;
            Bs[kk][nn] = X[(size_t)(k0 + kk) * NTOK + col0 + nn];
        }
        __syncthreads();
#pragma unroll
        for (int kk = 0; kk < 16; kk++) {
            float4 a4 = *(const float4*)&As[kk][ty * 4];
            float4 b4 = *(const float4*)&Bs[kk][tx * 4];
            float a[4] = {a4.x, a4.y, a4.z, a4.w};
            float b[4] = {b4.x, b4.y, b4.z, b4.w};
#pragma unroll
            for (int i = 0; i < 4; i++)
#pragma unroll
                for (int j = 0; j < 4; j++) acc[i][j] += a[i] * b[j];
        }
        __syncthreads();
    }

    const float qs = 0.17677669529663687f;
#pragma unroll
    for (int i = 0; i < 4; i++) {
        int r = row0 + ty * 4 + i;
#pragma unroll
        for (int j = 0; j < 4; j++) {
            int c = col0 + tx * 4 + j;
            float val = acc[i][j];
            if (bMat) val += bMat[(size_t)r * NTOK + c];
            if (op == 0) {
                Qh[((size_t)(b * 8 + (r >> 5)) * NTOK + c) * 32 + (r & 31)] = __float2half_rn(val * qs);
            } else if (op == 1) {
                Kh[((size_t)(b * 8 + (r >> 5)) * NTOK + c) * 32 + (r & 31)] = __float2half_rn(val);
            } else {
                Vh[((size_t)b * 256 + r) * NTOK + c] = __float2half_rn(val);
            }
        }
    }
}

// ================= warp-MMA flash attention =================
// Grid (18 qtiles, 32 bh), 128 threads (4 warps x 32 q rows).
// S = Q@K^T via m16n8k16 (f32 accum), exp (no-max; scores provably small), P fp16,
// O += P@V with a 33rd "ones" V row producing l in n-block 4.
__global__ void __launch_bounds__(128) attn_mma_kernel(const __half* __restrict__ Qh,
                                                       const __half* __restrict__ Kh,
                                                       const __half* __restrict__ Vh,
                                                       float* __restrict__ O) {
    __shared__ __half sQ[128][40];
    __shared__ __half sK[64][40];
    __shared__ __half sV[40][72];

    int tid = threadIdx.x, wid = tid >> 5, lane = tid & 31;
    int q0 = blockIdx.x * 128;
    int bh = blockIdx.y;

    // Q tile load: [q][d], 64B rows
#pragma unroll
    for (int c = 0; c < 4; c++) {
        int i = tid + c * 128;
        int row = i >> 2, ch = i & 3;
        *(uint4*)&sQ[row][ch * 8] =
            *(const uint4*)(Qh + ((size_t)bh * NTOK + q0 + row) * 32 + ch * 8);
    }
    // V static rows: row 32 = ones (l-column), rows 33-39 = zeros
    if (tid < 32) ((u32*)&sV[32][0])[tid] = 0x3C003C00u;
    for (int i = tid; i < 252; i += 128) ((u32*)&sV[33][0])[i] = 0u;
    __syncthreads();

    // Q fragments (held in regs for whole kernel)
    u32 qa[2][2][4];
#pragma unroll
    for (int m = 0; m < 2; m++)
#pragma unroll
        for (int ks = 0; ks < 2; ks++) {
            int r = wid * 32 + m * 16 + (lane >> 2);
            int cb = ks * 16 + (lane & 3) * 2;
            qa[m][ks][0] = *(u32*)&sQ[r][cb];
            qa[m][ks][1] = *(u32*)&sQ[r + 8][cb];
            qa[m][ks][2] = *(u32*)&sQ[r][cb + 8];
            qa[m][ks][3] = *(u32*)&sQ[r + 8][cb + 8];
        }

    float Oa[2][5][4];
#pragma unroll
    for (int m = 0; m < 2; m++)
#pragma unroll
        for (int n = 0; n < 5; n++)
#pragma unroll
            for (int c = 0; c < 4; c++) Oa[m][n][c] = 0.f;

#pragma unroll 1
    for (int kt = 0; kt < NKT; kt++) {
        int kb = kt * 64;
        if (kt > 0) __syncthreads();
        // K tile: 64 keys x 32 d
#pragma unroll
        for (int c = 0; c < 2; c++) {
            int i = tid + c * 128;
            int row = i >> 2, ch = i & 3;
            *(uint4*)&sK[row][ch * 8] =
                *(const uint4*)(Kh + ((size_t)bh * NTOK + kb + row) * 32 + ch * 8);
        }
        // V tile: 32 d rows x 64 keys
#pragma unroll
        for (int c = 0; c < 2; c++) {
            int i = tid + c * 128;
            int row = i >> 3, ch = i & 7;
            *(uint4*)&sV[row][ch * 8] =
                *(const uint4*)(Vh + ((size_t)bh * 32 + row) * NTOK + kb + ch * 8);
        }
        __syncthreads();

        // S = Q @ K^T  (32q x 64k per warp)
        float S[2][8][4];
#pragma unroll
        for (int m = 0; m < 2; m++)
#pragma unroll
            for (int n = 0; n < 8; n++)
#pragma unroll
                for (int c = 0; c < 4; c++) S[m][n][c] = 0.f;

#pragma unroll
        for (int nb = 0; nb < 8; nb++) {
            int key = nb * 8 + (lane >> 2);
#pragma unroll
            for (int ks = 0; ks < 2; ks++) {
                u32 b0 = *(u32*)&sK[key][ks * 16 + (lane & 3) * 2];
                u32 b1 = *(u32*)&sK[key][ks * 16 + 8 + (lane & 3) * 2];
                mma16816(S[0][nb], qa[0][ks][0], qa[0][ks][1], qa[0][ks][2], qa[0][ks][3], b0, b1);
                mma16816(S[1][nb], qa[1][ks][0], qa[1][ks][1], qa[1][ks][2], qa[1][ks][3], b0, b1);
            }
        }

        // P = exp(S) in fp16 (A-fragment layout == C layout)
        u32 P[2][8][2];
#pragma unroll
        for (int m = 0; m < 2; m++)
#pragma unroll
            for (int nb = 0; nb < 8; nb++) {
                P[m][nb][0] = f16pack(__expf(S[m][nb][0]), __expf(S[m][nb][1]));
                P[m][nb][1] = f16pack(__expf(S[m][nb][2]), __expf(S[m][nb][3]));
            }

        // O += P @ V  (n-blocks 0..3 = d, block 4 col0 = l via ones row)
#pragma unroll
        for (int nb5 = 0; nb5 < 5; nb5++) {
            int d = nb5 * 8 + (lane >> 2);
#pragma unroll
            for (int ks = 0; ks < 4; ks++) {
                u32 vb0 = *(u32*)&sV[d][ks * 16 + (lane & 3) * 2];
                u32 vb1 = *(u32*)&sV[d][ks * 16 + 8 + (lane & 3) * 2];
                mma16816(Oa[0][nb5], P[0][2 * ks][0], P[0][2 * ks][1],
                         P[0][2 * ks + 1][0], P[0][2 * ks + 1][1], vb0, vb1);
                mma16816(Oa[1][nb5], P[1][2 * ks][0], P[1][2 * ks][1],
                         P[1][2 * ks + 1][0], P[1][2 * ks + 1][1], vb0, vb1);
            }
        }
    }

    // normalize by l (col 32) and store
    int qb = q0 + wid * 32;
#pragma unroll
    for (int m = 0; m < 2; m++) {
        float li0 = 1.f / __shfl_sync(0xffffffffu, Oa[m][4][0], lane & ~3);
        float li1 = 1.f / __shfl_sync(0xffffffffu, Oa[m][4][2], lane & ~3);
        int r0 = qb + m * 16 + (lane >> 2);
#pragma unroll
        for (int nb = 0; nb < 4; nb++) {
            int d = nb * 8 + (lane & 3) * 2;
            size_t base = ((size_t)bh * 32 + d) * NTOK;
            O[base + r0]            = Oa[m][nb][0] * li0;
            O[base + NTOK + r0]     = Oa[m][nb][1] * li0;
            O[base + r0 + 8]        = Oa[m][nb][2] * li1;
            O[base + NTOK + r0 + 8] = Oa[m][nb][3] * li1;
        }
    }
}

// ================= batched GEMM =================
__global__ void gemm_kernel(const float* __restrict__ W, int ldw,
                            const float* __restrict__ X,
                            const float* __restrict__ bVec,
                            const float* __restrict__ resid,
                            float* __restrict__ out, int relu) {
    size_t off = (size_t)blockIdx.z * FEATC * NTOK;
    gemm_body(W, ldw, X + off, bVec, resid ? resid + off : nullptr, out + off, relu);
}

// ================= BN =================
__global__ void bnstats_kernel(const float* __restrict__ pre,
                               const float* __restrict__ gamma,
                               const float* __restrict__ beta) {
    int c = blockIdx.x;
    float s = 0.f, s2 = 0.f;
    for (int b = 0; b < 4; b++) {
        const float* p = pre + ((size_t)b * FEATC + c) * NTOK;
        for (int i = threadIdx.x; i < NTOK; i += 256) {
            float v = p[i];
            s += v;
            s2 += v * v;
        }
    }
    __shared__ float sh0[256], sh1[256];
    sh0[threadIdx.x] = s;
    sh1[threadIdx.x] = s2;
    __syncthreads();
    for (int st = 128; st > 0; st >>= 1) {
        if (threadIdx.x < st) {
            sh0[threadIdx.x] += sh0[threadIdx.x + st];
            sh1[threadIdx.x] += sh1[threadIdx.x + st];
        }
        __syncthreads();
    }
    if (threadIdx.x == 0) {
        const float n = 4.0f * NTOK;
        float mean = sh0[0] / n;
        float var = sh1[0] / n - mean * mean;
        float is = rsqrtf(var + 1e-5f);
        float scl = gamma[c] * is;
        g_scale[c] = scl;
        g_shift[c] = beta[c] - mean * scl;
    }
}

__global__ void bnapply_kernel(const float* __restrict__ pre, float* __restrict__ out) {
    int idx = blockIdx.x * 256 + threadIdx.x;
    if (idx >= 4 * FEATC * NTOK) return;
    int c = (idx / NTOK) & 255;
    out[idx] = pre[idx] * g_scale[c] + g_shift[c];
}

// ================= launch =================
extern "C" void kernel_launch(void* const* d_in, const int* in_sizes, int n_in,
                              void* d_out, int out_size) {
    const float* q     = (const float*)d_in[0];
    const float* k     = (const float*)d_in[1];
    const float* v     = (const float*)d_in[2];
    const float* wq    = (const float*)d_in[3];
    const float* wk    = (const float*)d_in[4];
    const float* wv    = (const float*)d_in[5];
    const float* wfc   = (const float*)d_in[6];
    const float* w1    = (const float*)d_in[7];
    const float* b1    = (const float*)d_in[8];
    const float* w2    = (const float*)d_in[9];
    const float* b2    = (const float*)d_in[10];
    const float* gamma = (const float*)d_in[11];
    const float* beta  = (const float*)d_in[12];
    float* out = (float*)d_out;

    float* base = nullptr;
    cudaGetSymbolAddress((void**)&base, g_scratch);
    float* pe  = base;
    float* bq  = base + 69120;
    float* bk  = bq + 589824;
    float* O   = bk + 589824;
    float* O2  = O + 2359296;
    float* H1  = O2 + 2359296;
    float* PRE = H1 + 2359296;
    __half* Qh = (__half*)(PRE + 2359296);
    __half* Kh = Qh + 2359296;
    __half* Vh = Kh + 2359296;

    pe_kernel<<<(30 * NTOK + 255) / 256, 256>>>(pe);
    {
        dim3 g(NTOK / 128, 256, 2);
        pebias_kernel<<<g, 128>>>(pe, wq, wk, bq, bk);
    }
    {
        dim3 g(NTOK / 64, FEATC / 64, 12);
        proj_kernel<<<g, 256>>>(wq, wk, wv, q, k, v, bq, bk, Qh, Kh, Vh);
    }
    {
        dim3 ga(NQT, 32);
        attn_mma_kernel<<<ga, 128>>>(Qh, Kh, Vh, O);
    }
    dim3 gg(NTOK / 64, FEATC / 64, 4);
    gemm_kernel<<<gg, 256>>>(wfc, 256, O, nullptr, nullptr, O2, 0);
    gemm_kernel<<<gg, 256>>>(w1, 256, O2, b1, nullptr, H1, 1);
    gemm_kernel<<<gg, 256>>>(w2, 256, H1, b2, O2, PRE, 0);
    bnstats_kernel<<<256, 256>>>(PRE, gamma, beta);
    bnapply_kernel<<<(4 * FEATC * NTOK + 255) / 256, 256>>>(PRE, out);
}

// round 7
// speedup vs baseline: 5.6575x; 1.2386x over previous
#include <cuda_runtime.h>
#include <cuda_fp16.h>
#include <math.h>

#define NTOK 2304
#define HWDIM 48
#define FEATC 256
#define NKT 36
#define NQT 18

typedef unsigned long long ull;
typedef unsigned int u32;

__device__ float g_scratch[17763840];
__device__ float g_scale[256];
__device__ float g_shift[256];

__device__ __forceinline__ u32 f16pack(float lo, float hi) {
    u32 r;
    asm("cvt.rn.f16x2.f32 %0, %1, %2;" : "=r"(r) : "f"(hi), "f"(lo));
    return r;
}
__device__ __forceinline__ void mma16816(float* d, u32 a0, u32 a1, u32 a2, u32 a3,
                                         u32 b0, u32 b1) {
    asm volatile(
        "mma.sync.aligned.m16n8k16.row.col.f32.f16.f16.f32 "
        "{%0,%1,%2,%3},{%4,%5,%6,%7},{%8,%9},{%0,%1,%2,%3};"
        : "+f"(d[0]), "+f"(d[1]), "+f"(d[2]), "+f"(d[3])
        : "r"(a0), "r"(a1), "r"(a2), "r"(a3), "r"(b0), "r"(b1));
}

// ================= PE =================
__global__ void pe_kernel(float* __restrict__ pe) {
    int idx = blockIdx.x * blockDim.x + threadIdx.x;
    if (idx >= 30 * NTOK) return;
    int c = idx / NTOK, p = idx % NTOK;
    int i = p / HWDIM, j = p % HWDIM;
    const float SC = 6.283185307179586f;
    int axis = c / 10, t = c % 10;
    float e;
    if (axis == 0)      e = (float)(i + 1) / (HWDIM + 1e-6f) * SC;
    else if (axis == 1) e = (float)(j + 1) / (HWDIM + 1e-6f) * SC;
    else                e = SC;
    float freq = powf(10000.0f, (2.0f * (float)(t >> 1)) / 10.0f);
    float ph = e / freq;
    pe[idx] = (t & 1) ? cosf(ph) : sinf(ph);
}

__global__ void pebias_kernel(const float* __restrict__ pe,
                              const float* __restrict__ wq,
                              const float* __restrict__ wk,
                              float* __restrict__ bq,
                              float* __restrict__ bk) {
    int p = blockIdx.x * blockDim.x + threadIdx.x;
    int c = blockIdx.y;
    const float* w = (blockIdx.z == 0 ? wq : wk) + (size_t)c * 286 + 256;
    float* o = (blockIdx.z == 0 ? bq : bk);
    float s = 0.f;
#pragma unroll
    for (int j = 0; j < 30; j++) s += w[j] * pe[j * NTOK + p];
    o[(size_t)c * NTOK + p] = s;
}

// ================= weight conversion: 6 x [256][256] fp16 =================
__global__ void wconv_kernel(const float* __restrict__ wq, const float* __restrict__ wk,
                             const float* __restrict__ wv, const float* __restrict__ wfc,
                             const float* __restrict__ w1, const float* __restrict__ w2,
                             __half* __restrict__ W16) {
    int idx = blockIdx.x * 256 + threadIdx.x;
    if (idx >= 6 * 65536) return;
    int w = idx >> 16, r = (idx >> 8) & 255, c = idx & 255;
    float v;
    if (w == 0)      v = wq[(size_t)r * 286 + c];
    else if (w == 1) v = wk[(size_t)r * 286 + c];
    else if (w == 2) v = wv[(size_t)r * 256 + c];
    else if (w == 3) v = wfc[(size_t)r * 256 + c];
    else if (w == 4) v = w1[(size_t)r * 256 + c];
    else             v = w2[(size_t)r * 256 + c];
    W16[idx] = __float2half_rn(v);
}

// ================= input transpose+convert: [c][tok] f32 -> [tok][c] f16 =================
__global__ void xconv_kernel(const float* __restrict__ q, const float* __restrict__ k,
                             const float* __restrict__ v, __half* __restrict__ XIN) {
    __shared__ float tile[32][33];
    int z = blockIdx.z;            // op*4 + b
    int op = z >> 2, b = z & 3;
    const float* src = (op == 0 ? q : op == 1 ? k : v) + (size_t)b * FEATC * NTOK;
    __half* dst = XIN + (size_t)z * FEATC * NTOK;
    int t0 = blockIdx.x * 32, c0 = blockIdx.y * 32;
    int tx = threadIdx.x, ty = threadIdx.y;
#pragma unroll
    for (int i = 0; i < 4; i++) {
        int cy = ty + i * 8;
        tile[cy][tx] = src[(size_t)(c0 + cy) * NTOK + t0 + tx];
    }
    __syncthreads();
#pragma unroll
    for (int i = 0; i < 4; i++) {
        int tr = ty + i * 8;
        dst[(size_t)(t0 + tr) * 256 + c0 + tx] = __float2half_rn(tile[tx][tr]);
    }
}

// ================= HMMA GEMM body =================
// C[oc][tok] = W16[oc][256] @ XH[tok][256]^T. CTA 128x128, 8 warps of 64x32.
__device__ __forceinline__ void hgemm_body(const __half* __restrict__ W16,
                                           const __half* __restrict__ XH,
                                           const float* __restrict__ bMat,
                                           const float* __restrict__ bVec,
                                           const float* __restrict__ resid,
                                           float qscale, int relu,
                                           float* __restrict__ outF,
                                           __half* __restrict__ outTok,
                                           __half* __restrict__ outC,
                                           unsigned char* smem) {
    __half (*sW)[40] = (__half(*)[40])smem;
    __half (*sX)[40] = (__half(*)[40])(smem + 10240);
    int tid = threadIdx.x, wid = tid >> 5, lane = tid & 31;
    int wr = wid >> 2, wc = wid & 3;
    int oc0 = blockIdx.y * 128, t0 = blockIdx.x * 128;

    float acc[4][4][4];
#pragma unroll
    for (int m = 0; m < 4; m++)
#pragma unroll
        for (int n = 0; n < 4; n++)
#pragma unroll
            for (int c = 0; c < 4; c++) acc[m][n][c] = 0.f;

    for (int kk = 0; kk < 256; kk += 32) {
#pragma unroll
        for (int i = 0; i < 2; i++) {
            int idx = tid + i * 256;
            int row = idx >> 2, ch = idx & 3;
            *(uint4*)&sW[row][ch * 8] = *(const uint4*)(W16 + (size_t)(oc0 + row) * 256 + kk + ch * 8);
            *(uint4*)&sX[row][ch * 8] = *(const uint4*)(XH + (size_t)(t0 + row) * 256 + kk + ch * 8);
        }
        __syncthreads();
#pragma unroll
        for (int ks = 0; ks < 2; ks++) {
            int cb = ks * 16 + (lane & 3) * 2;
            u32 a[4][4], bfr[4][2];
#pragma unroll
            for (int m = 0; m < 4; m++) {
                int r = wr * 64 + m * 16 + (lane >> 2);
                a[m][0] = *(u32*)&sW[r][cb];
                a[m][1] = *(u32*)&sW[r + 8][cb];
                a[m][2] = *(u32*)&sW[r][cb + 8];
                a[m][3] = *(u32*)&sW[r + 8][cb + 8];
            }
#pragma unroll
            for (int n = 0; n < 4; n++) {
                int key = wc * 32 + n * 8 + (lane >> 2);
                bfr[n][0] = *(u32*)&sX[key][cb];
                bfr[n][1] = *(u32*)&sX[key][cb + 8];
            }
#pragma unroll
            for (int m = 0; m < 4; m++)
#pragma unroll
                for (int n = 0; n < 4; n++)
                    mma16816(acc[m][n], a[m][0], a[m][1], a[m][2], a[m][3], bfr[n][0], bfr[n][1]);
        }
        __syncthreads();
    }

    // epilogue
#pragma unroll
    for (int m = 0; m < 4; m++) {
#pragma unroll
        for (int n = 0; n < 4; n++) {
            int r0 = oc0 + wr * 64 + m * 16 + (lane >> 2);
            int r1 = r0 + 8;
            int cX = t0 + wc * 32 + n * 8 + (lane & 3) * 2;
            float v00 = acc[m][n][0], v01 = acc[m][n][1];
            float v10 = acc[m][n][2], v11 = acc[m][n][3];
            if (bMat) {
                v00 += bMat[(size_t)r0 * NTOK + cX];
                v01 += bMat[(size_t)r0 * NTOK + cX + 1];
                v10 += bMat[(size_t)r1 * NTOK + cX];
                v11 += bMat[(size_t)r1 * NTOK + cX + 1];
            }
            if (bVec) {
                float bv0 = bVec[r0], bv1 = bVec[r1];
                v00 += bv0; v01 += bv0; v10 += bv1; v11 += bv1;
            }
            if (relu) {
                v00 = fmaxf(v00, 0.f); v01 = fmaxf(v01, 0.f);
                v10 = fmaxf(v10, 0.f); v11 = fmaxf(v11, 0.f);
            }
            if (resid) {
                v00 += resid[(size_t)r0 * NTOK + cX];
                v01 += resid[(size_t)r0 * NTOK + cX + 1];
                v10 += resid[(size_t)r1 * NTOK + cX];
                v11 += resid[(size_t)r1 * NTOK + cX + 1];
            }
            v00 *= qscale; v01 *= qscale; v10 *= qscale; v11 *= qscale;
            acc[m][n][0] = v00; acc[m][n][1] = v01; acc[m][n][2] = v10; acc[m][n][3] = v11;
            if (outF) {
                *(float2*)(outF + (size_t)r0 * NTOK + cX) = make_float2(v00, v01);
                *(float2*)(outF + (size_t)r1 * NTOK + cX) = make_float2(v10, v11);
            }
            if (outC) {
                *(u32*)(outC + (size_t)r0 * NTOK + cX) = f16pack(v00, v01);
                *(u32*)(outC + (size_t)r1 * NTOK + cX) = f16pack(v10, v11);
            }
        }
    }
    if (outTok) {
        __half (*sT)[136] = (__half(*)[136])smem;
        __syncthreads();
#pragma unroll
        for (int m = 0; m < 4; m++)
#pragma unroll
            for (int n = 0; n < 4; n++) {
                int lr0 = wr * 64 + m * 16 + (lane >> 2);
                int lc = wc * 32 + n * 8 + (lane & 3) * 2;
                sT[lc][lr0]     = __float2half_rn(acc[m][n][0]);
                sT[lc + 1][lr0] = __float2half_rn(acc[m][n][1]);
                sT[lc][lr0 + 8]     = __float2half_rn(acc[m][n][2]);
                sT[lc + 1][lr0 + 8] = __float2half_rn(acc[m][n][3]);
            }
        __syncthreads();
#pragma unroll
        for (int i = 0; i < 8; i++) {
            int idx = tid + i * 256;
            int row = idx >> 4, ch = idx & 15;
            *(uint4*)(outTok + (size_t)(t0 + row) * 256 + oc0 + ch * 8) =
                *(uint4*)&sT[row][ch * 8];
        }
    }
}

// proj: z = b*3+op
__global__ void __launch_bounds__(256) proj_h_kernel(const __half* __restrict__ W16,
                                                     const __half* __restrict__ XIN,
                                                     const float* __restrict__ bq,
                                                     const float* __restrict__ bk,
                                                     __half* __restrict__ QH,
                                                     __half* __restrict__ KH,
                                                     __half* __restrict__ VH) {
    __shared__ __align__(16) unsigned char smem[34816];
    int z = blockIdx.z;
    int b = z / 3, op = z - 3 * b;
    const __half* W = W16 + (size_t)op * 65536;
    const __half* X = XIN + (size_t)(op * 4 + b) * 589824;
    const float* bMat = (op == 0) ? bq : (op == 1) ? bk : nullptr;
    float qs = (op == 0) ? 0.17677669529663687f : 1.0f;
    __half* oT = (op == 0) ? QH + (size_t)b * 589824 : (op == 1) ? KH + (size_t)b * 589824 : nullptr;
    __half* oC = (op == 2) ? VH + (size_t)b * 589824 : nullptr;
    hgemm_body(W, X, bMat, nullptr, nullptr, qs, 0, nullptr, oT, oC, smem);
}

// generic: z = batch
__global__ void __launch_bounds__(256) hgemm_kernel(const __half* __restrict__ W16,
                                                    const __half* __restrict__ XH,
                                                    const float* __restrict__ bVec,
                                                    const float* __restrict__ resid,
                                                    float* __restrict__ outF,
                                                    __half* __restrict__ outTok,
                                                    int relu) {
    __shared__ __align__(16) unsigned char smem[34816];
    size_t off = (size_t)blockIdx.z * 589824;
    hgemm_body(W16, XH + off, nullptr, bVec, resid ? resid + off : nullptr, 1.0f, relu,
               outF ? outF + off : nullptr, outTok ? outTok + off : nullptr, nullptr, smem);
}

// ================= warp-MMA flash attention (token-major Q/K, fp16 out) =================
__global__ void __launch_bounds__(128) attn_mma_kernel(const __half* __restrict__ QH,
                                                       const __half* __restrict__ KH,
                                                       const __half* __restrict__ VH,
                                                       __half* __restrict__ OH) {
    __shared__ __half sQ[128][40];
    __shared__ __half sK[64][40];
    __shared__ __half sV[40][72];

    int tid = threadIdx.x, wid = tid >> 5, lane = tid & 31;
    int q0 = blockIdx.x * 128;
    int bh = blockIdx.y;
    int b = bh >> 3, h = bh & 7;

#pragma unroll
    for (int c = 0; c < 4; c++) {
        int i = tid + c * 128;
        int row = i >> 2, ch = i & 3;
        *(uint4*)&sQ[row][ch * 8] =
            *(const uint4*)(QH + ((size_t)b * NTOK + q0 + row) * 256 + h * 32 + ch * 8);
    }
    if (tid < 32) ((u32*)&sV[32][0])[tid] = 0x3C003C00u;
    for (int i = tid; i < 252; i += 128) ((u32*)&sV[33][0])[i] = 0u;
    __syncthreads();

    u32 qa[2][2][4];
#pragma unroll
    for (int m = 0; m < 2; m++)
#pragma unroll
        for (int ks = 0; ks < 2; ks++) {
            int r = wid * 32 + m * 16 + (lane >> 2);
            int cb = ks * 16 + (lane & 3) * 2;
            qa[m][ks][0] = *(u32*)&sQ[r][cb];
            qa[m][ks][1] = *(u32*)&sQ[r + 8][cb];
            qa[m][ks][2] = *(u32*)&sQ[r][cb + 8];
            qa[m][ks][3] = *(u32*)&sQ[r + 8][cb + 8];
        }

    float Oa[2][5][4];
#pragma unroll
    for (int m = 0; m < 2; m++)
#pragma unroll
        for (int n = 0; n < 5; n++)
#pragma unroll
            for (int c = 0; c < 4; c++) Oa[m][n][c] = 0.f;

#pragma unroll 1
    for (int kt = 0; kt < NKT; kt++) {
        int kb = kt * 64;
        if (kt > 0) __syncthreads();
#pragma unroll
        for (int c = 0; c < 2; c++) {
            int i = tid + c * 128;
            int row = i >> 2, ch = i & 3;
            *(uint4*)&sK[row][ch * 8] =
                *(const uint4*)(KH + ((size_t)b * NTOK + kb + row) * 256 + h * 32 + ch * 8);
        }
#pragma unroll
        for (int c = 0; c < 2; c++) {
            int i = tid + c * 128;
            int row = i >> 3, ch = i & 7;
            *(uint4*)&sV[row][ch * 8] =
                *(const uint4*)(VH + ((size_t)(b * 256 + h * 32 + row)) * NTOK + kb + ch * 8);
        }
        __syncthreads();

        float S[2][8][4];
#pragma unroll
        for (int m = 0; m < 2; m++)
#pragma unroll
            for (int n = 0; n < 8; n++)
#pragma unroll
                for (int c = 0; c < 4; c++) S[m][n][c] = 0.f;

#pragma unroll
        for (int nb = 0; nb < 8; nb++) {
            int key = nb * 8 + (lane >> 2);
#pragma unroll
            for (int ks = 0; ks < 2; ks++) {
                u32 b0 = *(u32*)&sK[key][ks * 16 + (lane & 3) * 2];
                u32 b1 = *(u32*)&sK[key][ks * 16 + 8 + (lane & 3) * 2];
                mma16816(S[0][nb], qa[0][ks][0], qa[0][ks][1], qa[0][ks][2], qa[0][ks][3], b0, b1);
                mma16816(S[1][nb], qa[1][ks][0], qa[1][ks][1], qa[1][ks][2], qa[1][ks][3], b0, b1);
            }
        }

        u32 P[2][8][2];
#pragma unroll
        for (int m = 0; m < 2; m++)
#pragma unroll
            for (int nb = 0; nb < 8; nb++) {
                P[m][nb][0] = f16pack(__expf(S[m][nb][0]), __expf(S[m][nb][1]));
                P[m][nb][1] = f16pack(__expf(S[m][nb][2]), __expf(S[m][nb][3]));
            }

#pragma unroll
        for (int nb5 = 0; nb5 < 5; nb5++) {
            int d = nb5 * 8 + (lane >> 2);
#pragma unroll
            for (int ks = 0; ks < 4; ks++) {
                u32 vb0 = *(u32*)&sV[d][ks * 16 + (lane & 3) * 2];
                u32 vb1 = *(u32*)&sV[d][ks * 16 + 8 + (lane & 3) * 2];
                mma16816(Oa[0][nb5], P[0][2 * ks][0], P[0][2 * ks][1],
                         P[0][2 * ks + 1][0], P[0][2 * ks + 1][1], vb0, vb1);
                mma16816(Oa[1][nb5], P[1][2 * ks][0], P[1][2 * ks][1],
                         P[1][2 * ks + 1][0], P[1][2 * ks + 1][1], vb0, vb1);
            }
        }
    }

    int qb = q0 + wid * 32;
#pragma unroll
    for (int m = 0; m < 2; m++) {
        float li0 = 1.f / __shfl_sync(0xffffffffu, Oa[m][4][0], lane & ~3);
        float li1 = 1.f / __shfl_sync(0xffffffffu, Oa[m][4][2], lane & ~3);
        int r0 = qb + m * 16 + (lane >> 2);
#pragma unroll
        for (int nb = 0; nb < 4; nb++) {
            int d = nb * 8 + (lane & 3) * 2;
            *(u32*)(OH + ((size_t)b * NTOK + r0) * 256 + h * 32 + d) =
                f16pack(Oa[m][nb][0] * li0, Oa[m][nb][1] * li0);
            *(u32*)(OH + ((size_t)b * NTOK + r0 + 8) * 256 + h * 32 + d) =
                f16pack(Oa[m][nb][2] * li1, Oa[m][nb][3] * li1);
        }
    }
}

// ================= BN =================
__global__ void bnstats_kernel(const float* __restrict__ pre,
                               const float* __restrict__ gamma,
                               const float* __restrict__ beta) {
    int c = blockIdx.x;
    float s = 0.f, s2 = 0.f;
    for (int b = 0; b < 4; b++) {
        const float* p = pre + ((size_t)b * FEATC + c) * NTOK;
        for (int i = threadIdx.x; i < NTOK; i += 256) {
            float v = p[i];
            s += v;
            s2 += v * v;
        }
    }
    __shared__ float sh0[256], sh1[256];
    sh0[threadIdx.x] = s;
    sh1[threadIdx.x] = s2;
    __syncthreads();
    for (int st = 128; st > 0; st >>= 1) {
        if (threadIdx.x < st) {
            sh0[threadIdx.x] += sh0[threadIdx.x + st];
            sh1[threadIdx.x] += sh1[threadIdx.x + st];
        }
        __syncthreads();
    }
    if (threadIdx.x == 0) {
        const float n = 4.0f * NTOK;
        float mean = sh0[0] / n;
        float var = sh1[0] / n - mean * mean;
        float is = rsqrtf(var + 1e-5f);
        float scl = gamma[c] * is;
        g_scale[c] = scl;
        g_shift[c] = beta[c] - mean * scl;
    }
}

__global__ void bnapply_kernel(const float* __restrict__ pre, float* __restrict__ out) {
    int idx = blockIdx.x * 256 + threadIdx.x;
    if (idx >= 4 * FEATC * NTOK) return;
    int c = (idx / NTOK) & 255;
    out[idx] = pre[idx] * g_scale[c] + g_shift[c];
}

// ================= launch =================
extern "C" void kernel_launch(void* const* d_in, const int* in_sizes, int n_in,
                              void* d_out, int out_size) {
    const float* q     = (const float*)d_in[0];
    const float* k     = (const float*)d_in[1];
    const float* v     = (const float*)d_in[2];
    const float* wq    = (const float*)d_in[3];
    const float* wk    = (const float*)d_in[4];
    const float* wv    = (const float*)d_in[5];
    const float* wfc   = (const float*)d_in[6];
    const float* w1    = (const float*)d_in[7];
    const float* b1    = (const float*)d_in[8];
    const float* w2    = (const float*)d_in[9];
    const float* b2    = (const float*)d_in[10];
    const float* gamma = (const float*)d_in[11];
    const float* beta  = (const float*)d_in[12];
    float* out = (float*)d_out;

    float* base = nullptr;
    cudaGetSymbolAddress((void**)&base, g_scratch);
    float* pe  = base;                  // 69120
    float* bq  = base + 69120;          // 589824
    float* bk  = base + 658944;         // 589824
    float* O2  = base + 1248768;        // 2359296
    float* PRE = base + 3608064;        // 2359296
    __half* hb  = (__half*)(base + 5967360);
    __half* W16 = hb;                   // 393216
    __half* XIN = hb + 393216;          // 7077888
    __half* QH  = hb + 7471104;         // 2359296
    __half* KH  = hb + 9830400;
    __half* VH  = hb + 12189696;
    __half* OH  = hb + 14548992;
    __half* O2h = hb + 16908288;
    __half* H1h = hb + 19267584;

    pe_kernel<<<(30 * NTOK + 255) / 256, 256>>>(pe);
    {
        dim3 g(NTOK / 128, 256, 2);
        pebias_kernel<<<g, 128>>>(pe, wq, wk, bq, bk);
    }
    wconv_kernel<<<(6 * 65536) / 256, 256>>>(wq, wk, wv, wfc, w1, w2, W16);
    {
        dim3 g(NTOK / 32, FEATC / 32, 12);
        xconv_kernel<<<g, dim3(32, 8)>>>(q, k, v, XIN);
    }
    {
        dim3 g(NTOK / 128, 2, 12);
        proj_h_kernel<<<g, 256>>>(W16, XIN, bq, bk, QH, KH, VH);
    }
    {
        dim3 ga(NQT, 32);
        attn_mma_kernel<<<ga, 128>>>(QH, KH, VH, OH);
    }
    {
        dim3 g(NTOK / 128, 2, 4);
        hgemm_kernel<<<g, 256>>>(W16 + 3 * 65536, OH, nullptr, nullptr, O2, O2h, 0);
        hgemm_kernel<<<g, 256>>>(W16 + 4 * 65536, O2h, b1, nullptr, nullptr, H1h, 1);
        hgemm_kernel<<<g, 256>>>(W16 + 5 * 65536, H1h, b2, O2, PRE, nullptr, 0);
    }
    bnstats_kernel<<<256, 256>>>(PRE, gamma, beta);
    bnapply_kernel<<<(4 * FEATC * NTOK + 255) / 256, 256>>>(PRE, out);
}

// round 10
// speedup vs baseline: 10.0948x; 1.7843x over previous
#include <cuda_runtime.h>
#include <cuda_fp16.h>
#include <math.h>

#define NTOK 2304
#define HWDIM 48
#define FEATC 256
#define NKT 36
#define NQT 18

typedef unsigned long long ull;
typedef unsigned int u32;

__device__ float g_scratch[17763840];
__device__ float g_scale[256];
__device__ float g_shift[256];

__device__ __forceinline__ u32 f16pack(float lo, float hi) {
    u32 r;
    asm("cvt.rn.f16x2.f32 %0, %1, %2;" : "=r"(r) : "f"(hi), "f"(lo));
    return r;
}
__device__ __forceinline__ u32 ex2h2(u32 x) {
    u32 r;
    asm("ex2.approx.f16x2 %0, %1;" : "=r"(r) : "r"(x));
    return r;
}
__device__ __forceinline__ void mma16816(float* d, u32 a0, u32 a1, u32 a2, u32 a3,
                                         u32 b0, u32 b1) {
    asm volatile(
        "mma.sync.aligned.m16n8k16.row.col.f32.f16.f16.f32 "
        "{%0,%1,%2,%3},{%4,%5,%6,%7},{%8,%9},{%0,%1,%2,%3};"
        : "+f"(d[0]), "+f"(d[1]), "+f"(d[2]), "+f"(d[3])
        : "r"(a0), "r"(a1), "r"(a2), "r"(a3), "r"(b0), "r"(b1));
}

// ================= PE -> fp16 channels appended to XIN q/k slices =================
// XIN layout: q slices b0-3 [tok][288], k slices b0-3 [tok][288], v slices b0-3 [tok][256]
__global__ void pe16_kernel(__half* __restrict__ XIN) {
    int idx = blockIdx.x * 256 + threadIdx.x;
    if (idx >= 32 * NTOK) return;
    int tok = idx >> 5, c = idx & 31;
    float val = 0.f;
    if (c < 30) {
        int i = tok / HWDIM, j = tok % HWDIM;
        const float SC = 6.283185307179586f;
        int axis = c / 10, t = c % 10;
        float e;
        if (axis == 0)      e = (float)(i + 1) / (HWDIM + 1e-6f) * SC;
        else if (axis == 1) e = (float)(j + 1) / (HWDIM + 1e-6f) * SC;
        else                e = SC;
        float freq = powf(10000.0f, (2.0f * (float)(t >> 1)) / 10.0f);
        float ph = e / freq;
        val = (t & 1) ? cosf(ph) : sinf(ph);
    }
    __half h = __float2half_rn(val);
#pragma unroll
    for (int s = 0; s < 8; s++)
        XIN[(size_t)s * 663552 + (size_t)tok * 288 + 256 + c] = h;
}

// ================= weight conversion =================
// W16: wq[256][288], wk[256][288] (cols 286-287 zero), then wv/wfc/w1/w2 [256][256]
__global__ void wconv_kernel(const float* __restrict__ wq, const float* __restrict__ wk,
                             const float* __restrict__ wv, const float* __restrict__ wfc,
                             const float* __restrict__ w1, const float* __restrict__ w2,
                             __half* __restrict__ W16) {
    int idx = blockIdx.x * 256 + threadIdx.x;
    if (idx >= 409600) return;
    float v;
    if (idx < 147456) {
        int w = idx / 73728;
        int rem = idx - w * 73728;
        int r = rem / 288, c = rem - r * 288;
        const float* src = w ? wk : wq;
        v = (c < 286) ? src[(size_t)r * 286 + c] : 0.f;
    } else {
        int idx2 = idx - 147456;
        int w = idx2 >> 16, r = (idx2 >> 8) & 255, c = idx2 & 255;
        const float* src = (w == 0) ? wv : (w == 1) ? wfc : (w == 2) ? w1 : w2;
        v = src[(size_t)r * 256 + c];
    }
    W16[idx] = __float2half_rn(v);
}

// ================= input transpose+convert (vectorized) =================
// [c][tok] f32 -> [tok][c] f16 ; block: 32 channels x 128 tokens
__global__ void __launch_bounds__(256) xconv_kernel(const float* __restrict__ q,
                                                    const float* __restrict__ k,
                                                    const float* __restrict__ v,
                                                    __half* __restrict__ XIN) {
    __shared__ float tile[32][132];
    int z = blockIdx.z;            // op*4 + b
    int op = z >> 2, b = z & 3;
    const float* src = (op == 0 ? q : op == 1 ? k : v) + (size_t)b * FEATC * NTOK;
    int ldx = (op == 2) ? 256 : 288;
    __half* dst = XIN + (op == 2 ? (size_t)8 * 663552 + (size_t)b * 589824
                                 : (size_t)(op * 4 + b) * 663552);
    int t0 = blockIdx.x * 128, c0 = blockIdx.y * 32;
    int tid = threadIdx.x;
#pragma unroll
    for (int j = 0; j < 4; j++) {
        int i = tid + j * 256;
        int row = i >> 5, f4 = i & 31;
        float4 vv = *(const float4*)(src + (size_t)(c0 + row) * NTOK + t0 + f4 * 4);
        tile[row][f4 * 4] = vv.x;
        tile[row][f4 * 4 + 1] = vv.y;
        tile[row][f4 * 4 + 2] = vv.z;
        tile[row][f4 * 4 + 3] = vv.w;
    }
    __syncthreads();
#pragma unroll
    for (int j = 0; j < 2; j++) {
        int i = tid + j * 256;
        int tok = i >> 2, q4 = i & 3;
        u32 out4[4];
#pragma unroll
        for (int p = 0; p < 4; p++) {
            int c = q4 * 8 + p * 2;
            out4[p] = f16pack(tile[c][tok], tile[c + 1][tok]);
        }
        *(uint4*)(dst + (size_t)(t0 + tok) * ldx + c0 + q4 * 8) = *(uint4*)out4;
    }
}

// ================= HMMA GEMM body =================
// C[oc][tok] = W16[oc][kdim] @ XH[tok][kdim]^T. CTA 128x128, 8 warps 64x32.
__device__ __forceinline__ void hgemm_body(const __half* __restrict__ W16, int kdim,
                                           const __half* __restrict__ XH, int ldx,
                                           const float* __restrict__ bVec,
                                           const float* __restrict__ resid,
                                           float qscale, int relu,
                                           float* __restrict__ outF,
                                           __half* __restrict__ outTok,
                                           __half* __restrict__ outC,
                                           unsigned char* smem) {
    __half (*sW)[40] = (__half(*)[40])smem;
    __half (*sX)[40] = (__half(*)[40])(smem + 10240);
    int tid = threadIdx.x, wid = tid >> 5, lane = tid & 31;
    int wr = wid >> 2, wc = wid & 3;
    int oc0 = blockIdx.y * 128, t0 = blockIdx.x * 128;

    float acc[4][4][4];
#pragma unroll
    for (int m = 0; m < 4; m++)
#pragma unroll
        for (int n = 0; n < 4; n++)
#pragma unroll
            for (int c = 0; c < 4; c++) acc[m][n][c] = 0.f;

    for (int kk = 0; kk < kdim; kk += 32) {
#pragma unroll
        for (int i = 0; i < 2; i++) {
            int idx = tid + i * 256;
            int row = idx >> 2, ch = idx & 3;
            *(uint4*)&sW[row][ch * 8] = *(const uint4*)(W16 + (size_t)(oc0 + row) * kdim + kk + ch * 8);
            *(uint4*)&sX[row][ch * 8] = *(const uint4*)(XH + (size_t)(t0 + row) * ldx + kk + ch * 8);
        }
        __syncthreads();
#pragma unroll
        for (int ks = 0; ks < 2; ks++) {
            int cb = ks * 16 + (lane & 3) * 2;
            u32 a[4][4], bfr[4][2];
#pragma unroll
            for (int m = 0; m < 4; m++) {
                int r = wr * 64 + m * 16 + (lane >> 2);
                a[m][0] = *(u32*)&sW[r][cb];
                a[m][1] = *(u32*)&sW[r + 8][cb];
                a[m][2] = *(u32*)&sW[r][cb + 8];
                a[m][3] = *(u32*)&sW[r + 8][cb + 8];
            }
#pragma unroll
            for (int n = 0; n < 4; n++) {
                int key = wc * 32 + n * 8 + (lane >> 2);
                bfr[n][0] = *(u32*)&sX[key][cb];
                bfr[n][1] = *(u32*)&sX[key][cb + 8];
            }
#pragma unroll
            for (int m = 0; m < 4; m++)
#pragma unroll
                for (int n = 0; n < 4; n++)
                    mma16816(acc[m][n], a[m][0], a[m][1], a[m][2], a[m][3], bfr[n][0], bfr[n][1]);
        }
        __syncthreads();
    }

#pragma unroll
    for (int m = 0; m < 4; m++) {
#pragma unroll
        for (int n = 0; n < 4; n++) {
            int r0 = oc0 + wr * 64 + m * 16 + (lane >> 2);
            int r1 = r0 + 8;
            int cX = t0 + wc * 32 + n * 8 + (lane & 3) * 2;
            float v00 = acc[m][n][0], v01 = acc[m][n][1];
            float v10 = acc[m][n][2], v11 = acc[m][n][3];
            if (bVec) {
                float bv0 = bVec[r0], bv1 = bVec[r1];
                v00 += bv0; v01 += bv0; v10 += bv1; v11 += bv1;
            }
            if (relu) {
                v00 = fmaxf(v00, 0.f); v01 = fmaxf(v01, 0.f);
                v10 = fmaxf(v10, 0.f); v11 = fmaxf(v11, 0.f);
            }
            if (resid) {
                v00 += resid[(size_t)r0 * NTOK + cX];
                v01 += resid[(size_t)r0 * NTOK + cX + 1];
                v10 += resid[(size_t)r1 * NTOK + cX];
                v11 += resid[(size_t)r1 * NTOK + cX + 1];
            }
            v00 *= qscale; v01 *= qscale; v10 *= qscale; v11 *= qscale;
            acc[m][n][0] = v00; acc[m][n][1] = v01; acc[m][n][2] = v10; acc[m][n][3] = v11;
            if (outF) {
                *(float2*)(outF + (size_t)r0 * NTOK + cX) = make_float2(v00, v01);
                *(float2*)(outF + (size_t)r1 * NTOK + cX) = make_float2(v10, v11);
            }
            if (outC) {
                *(u32*)(outC + (size_t)r0 * NTOK + cX) = f16pack(v00, v01);
                *(u32*)(outC + (size_t)r1 * NTOK + cX) = f16pack(v10, v11);
            }
        }
    }
    if (outTok) {
        __half (*sT)[136] = (__half(*)[136])smem;
        __syncthreads();
#pragma unroll
        for (int m = 0; m < 4; m++)
#pragma unroll
            for (int n = 0; n < 4; n++) {
                int lr0 = wr * 64 + m * 16 + (lane >> 2);
                int lc = wc * 32 + n * 8 + (lane & 3) * 2;
                sT[lc][lr0]     = __float2half_rn(acc[m][n][0]);
                sT[lc + 1][lr0] = __float2half_rn(acc[m][n][1]);
                sT[lc][lr0 + 8]     = __float2half_rn(acc[m][n][2]);
                sT[lc + 1][lr0 + 8] = __float2half_rn(acc[m][n][3]);
            }
        __syncthreads();
#pragma unroll
        for (int i = 0; i < 8; i++) {
            int idx = tid + i * 256;
            int row = idx >> 4, ch = idx & 15;
            *(uint4*)(outTok + (size_t)(t0 + row) * 256 + oc0 + ch * 8) =
                *(uint4*)&sT[row][ch * 8];
        }
    }
}

// proj: z = op*4 + b ; Q gets 1/sqrt(32)*log2(e) folded in
__global__ void __launch_bounds__(256) proj_h_kernel(const __half* __restrict__ W16,
                                                     const __half* __restrict__ XIN,
                                                     __half* __restrict__ QH,
                                                     __half* __restrict__ KH,
                                                     __half* __restrict__ VH) {
    __shared__ __align__(16) unsigned char smem[34816];
    int z = blockIdx.z;
    int op = z >> 2, b = z & 3;
    if (op == 0) {
        hgemm_body(W16, 288, XIN + (size_t)b * 663552, 288, nullptr, nullptr,
                   0.2550348634f, 0, nullptr, QH + (size_t)b * 589824, nullptr, smem);
    } else if (op == 1) {
        hgemm_body(W16 + 73728, 288, XIN + (size_t)(4 + b) * 663552, 288, nullptr, nullptr,
                   1.0f, 0, nullptr, KH + (size_t)b * 589824, nullptr, smem);
    } else {
        hgemm_body(W16 + 147456, 256, XIN + (size_t)8 * 663552 + (size_t)b * 589824, 256,
                   nullptr, nullptr, 1.0f, 0, nullptr, nullptr, VH + (size_t)b * 589824, smem);
    }
}

__global__ void __launch_bounds__(256) hgemm_kernel(const __half* __restrict__ W16,
                                                    const __half* __restrict__ XH,
                                                    const float* __restrict__ bVec,
                                                    const float* __restrict__ resid,
                                                    float* __restrict__ outF,
                                                    __half* __restrict__ outTok,
                                                    int relu) {
    __shared__ __align__(16) unsigned char smem[34816];
    size_t off = (size_t)blockIdx.z * 589824;
    hgemm_body(W16, 256, XH + off, 256, bVec, resid ? resid + off : nullptr, 1.0f, relu,
               outF ? outF + off : nullptr, outTok ? outTok + off : nullptr, nullptr, smem);
}

// ================= warp-MMA flash attention (ex2.f16x2 softmax) =================
__global__ void __launch_bounds__(128) attn_mma_kernel(const __half* __restrict__ QH,
                                                       const __half* __restrict__ KH,
                                                       const __half* __restrict__ VH,
                                                       __half* __restrict__ OH) {
    __shared__ __half sQ[128][40];
    __shared__ __half sK[64][40];
    __shared__ __half sV[40][72];

    int tid = threadIdx.x, wid = tid >> 5, lane = tid & 31;
    int q0 = blockIdx.x * 128;
    int bh = blockIdx.y;
    int b = bh >> 3, h = bh & 7;

#pragma unroll
    for (int c = 0; c < 4; c++) {
        int i = tid + c * 128;
        int row = i >> 2, ch = i & 3;
        *(uint4*)&sQ[row][ch * 8] =
            *(const uint4*)(QH + ((size_t)b * NTOK + q0 + row) * 256 + h * 32 + ch * 8);
    }
    if (tid < 32) ((u32*)&sV[32][0])[tid] = 0x3C003C00u;
    for (int i = tid; i < 252; i += 128) ((u32*)&sV[33][0])[i] = 0u;
    __syncthreads();

    u32 qa[2][2][4];
#pragma unroll
    for (int m = 0; m < 2; m++)
#pragma unroll
        for (int ks = 0; ks < 2; ks++) {
            int r = wid * 32 + m * 16 + (lane >> 2);
            int cb = ks * 16 + (lane & 3) * 2;
            qa[m][ks][0] = *(u32*)&sQ[r][cb];
            qa[m][ks][1] = *(u32*)&sQ[r + 8][cb];
            qa[m][ks][2] = *(u32*)&sQ[r][cb + 8];
            qa[m][ks][3] = *(u32*)&sQ[r + 8][cb + 8];
        }

    float Oa[2][5][4];
#pragma unroll
    for (int m = 0; m < 2; m++)
#pragma unroll
        for (int n = 0; n < 5; n++)
#pragma unroll
            for (int c = 0; c < 4; c++) Oa[m][n][c] = 0.f;

#pragma unroll 1
    for (int kt = 0; kt < NKT; kt++) {
        int kb = kt * 64;
        if (kt > 0) __syncthreads();
#pragma unroll
        for (int c = 0; c < 2; c++) {
            int i = tid + c * 128;
            int row = i >> 2, ch = i & 3;
            *(uint4*)&sK[row][ch * 8] =
                *(const uint4*)(KH + ((size_t)b * NTOK + kb + row) * 256 + h * 32 + ch * 8);
        }
#pragma unroll
        for (int c = 0; c < 2; c++) {
            int i = tid + c * 128;
            int row = i >> 3, ch = i & 7;
            *(uint4*)&sV[row][ch * 8] =
                *(const uint4*)(VH + ((size_t)(b * 256 + h * 32 + row)) * NTOK + kb + ch * 8);
        }
        __syncthreads();

        float S[2][8][4];
#pragma unroll
        for (int m = 0; m < 2; m++)
#pragma unroll
            for (int n = 0; n < 8; n++)
#pragma unroll
                for (int c = 0; c < 4; c++) S[m][n][c] = 0.f;

#pragma unroll
        for (int nb = 0; nb < 8; nb++) {
            int key = nb * 8 + (lane >> 2);
#pragma unroll
            for (int ks = 0; ks < 2; ks++) {
                u32 b0 = *(u32*)&sK[key][ks * 16 + (lane & 3) * 2];
                u32 b1 = *(u32*)&sK[key][ks * 16 + 8 + (lane & 3) * 2];
                mma16816(S[0][nb], qa[0][ks][0], qa[0][ks][1], qa[0][ks][2], qa[0][ks][3], b0, b1);
                mma16816(S[1][nb], qa[1][ks][0], qa[1][ks][1], qa[1][ks][2], qa[1][ks][3], b0, b1);
            }
        }

        // P = 2^S (S already in log2 domain) via ex2.approx.f16x2
        u32 P[2][8][2];
#pragma unroll
        for (int m = 0; m < 2; m++)
#pragma unroll
            for (int nb = 0; nb < 8; nb++) {
                P[m][nb][0] = ex2h2(f16pack(S[m][nb][0], S[m][nb][1]));
                P[m][nb][1] = ex2h2(f16pack(S[m][nb][2], S[m][nb][3]));
            }

#pragma unroll
        for (int nb5 = 0; nb5 < 5; nb5++) {
            int d = nb5 * 8 + (lane >> 2);
#pragma unroll
            for (int ks = 0; ks < 4; ks++) {
                u32 vb0 = *(u32*)&sV[d][ks * 16 + (lane & 3) * 2];
                u32 vb1 = *(u32*)&sV[d][ks * 16 + 8 + (lane & 3) * 2];
                mma16816(Oa[0][nb5], P[0][2 * ks][0], P[0][2 * ks][1],
                         P[0][2 * ks + 1][0], P[0][2 * ks + 1][1], vb0, vb1);
                mma16816(Oa[1][nb5], P[1][2 * ks][0], P[1][2 * ks][1],
                         P[1][2 * ks + 1][0], P[1][2 * ks + 1][1], vb0, vb1);
            }
        }
    }

    int qb = q0 + wid * 32;
#pragma unroll
    for (int m = 0; m < 2; m++) {
        float li0 = 1.f / __shfl_sync(0xffffffffu, Oa[m][4][0], lane & ~3);
        float li1 = 1.f / __shfl_sync(0xffffffffu, Oa[m][4][2], lane & ~3);
        int r0 = qb + m * 16 + (lane >> 2);
#pragma unroll
        for (int nb = 0; nb < 4; nb++) {
            int d = nb * 8 + (lane & 3) * 2;
            *(u32*)(OH + ((size_t)b * NTOK + r0) * 256 + h * 32 + d) =
                f16pack(Oa[m][nb][0] * li0, Oa[m][nb][1] * li0);
            *(u32*)(OH + ((size_t)b * NTOK + r0 + 8) * 256 + h * 32 + d) =
                f16pack(Oa[m][nb][2] * li1, Oa[m][nb][3] * li1);
        }
    }
}

// ================= BN =================
__global__ void bnstats_kernel(const float* __restrict__ pre,
                               const float* __restrict__ gamma,
                               const float* __restrict__ beta) {
    int c = blockIdx.x;
    float s = 0.f, s2 = 0.f;
    for (int b = 0; b < 4; b++) {
        const float* p = pre + ((size_t)b * FEATC + c) * NTOK;
        for (int i = threadIdx.x; i < NTOK / 4; i += 256) {
            float4 v = ((const float4*)p)[i];
            s += v.x + v.y + v.z + v.w;
            s2 += v.x * v.x + v.y * v.y + v.z * v.z + v.w * v.w;
        }
    }
    __shared__ float sh0[256], sh1[256];
    sh0[threadIdx.x] = s;
    sh1[threadIdx.x] = s2;
    __syncthreads();
    for (int st = 128; st > 0; st >>= 1) {
        if (threadIdx.x < st) {
            sh0[threadIdx.x] += sh0[threadIdx.x + st];
            sh1[threadIdx.x] += sh1[threadIdx.x + st];
        }
        __syncthreads();
    }
    if (threadIdx.x == 0) {
        const float n = 4.0f * NTOK;
        float mean = sh0[0] / n;
        float var = sh1[0] / n - mean * mean;
        float is = rsqrtf(var + 1e-5f);
        float scl = gamma[c] * is;
        g_scale[c] = scl;
        g_shift[c] = beta[c] - mean * scl;
    }
}

// float4-vectorized; 589824 float4 chunks total (4*256*2304 floats / 4)
__global__ void bnapply_kernel(const float* __restrict__ pre, float* __restrict__ out) {
    int idx = blockIdx.x * 256 + threadIdx.x;   // float4 index
    if (idx >= 589824) return;
    int c = ((idx << 2) / NTOK) & 255;
    float sc = g_scale[c], sh = g_shift[c];
    float4 v = ((const float4*)pre)[idx];
    v.x = v.x * sc + sh; v.y = v.y * sc + sh;
    v.z = v.z * sc + sh; v.w = v.w * sc + sh;
    ((float4*)out)[idx] = v;
}

// ================= launch =================
extern "C" void kernel_launch(void* const* d_in, const int* in_sizes, int n_in,
                              void* d_out, int out_size) {
    const float* q     = (const float*)d_in[0];
    const float* k     = (const float*)d_in[1];
    const float* v     = (const float*)d_in[2];
    const float* wq    = (const float*)d_in[3];
    const float* wk    = (const float*)d_in[4];
    const float* wv    = (const float*)d_in[5];
    const float* wfc   = (const float*)d_in[6];
    const float* w1    = (const float*)d_in[7];
    const float* b1    = (const float*)d_in[8];
    const float* w2    = (const float*)d_in[9];
    const float* b2    = (const float*)d_in[10];
    const float* gamma = (const float*)d_in[11];
    const float* beta  = (const float*)d_in[12];
    float* out = (float*)d_out;

    float* base = nullptr;
    cudaGetSymbolAddress((void**)&base, g_scratch);
    float* O2  = base;                  // 2359296
    float* PRE = base + 2359296;        // 2359296
    __half* hb  = (__half*)(base + 4718592);
    __half* W16 = hb;                   // 409600
    __half* XIN = hb + 409600;          // 7667712
    __half* QH  = hb + 8077312;         // 2359296 each
    __half* KH  = QH + 2359296;
    __half* VH  = KH + 2359296;
    __half* OH  = VH + 2359296;
    __half* O2h = OH + 2359296;
    __half* H1h = O2h + 2359296;

    pe16_kernel<<<(32 * NTOK + 255) / 256, 256>>>(XIN);
    wconv_kernel<<<1600, 256>>>(wq, wk, wv, wfc, w1, w2, W16);
    {
        dim3 g(NTOK / 128, FEATC / 32, 12);
        xconv_kernel<<<g, 256>>>(q, k, v, XIN);
    }
    {
        dim3 g(NTOK / 128, 2, 12);
        proj_h_kernel<<<g, 256>>>(W16, XIN, QH, KH, VH);
    }
    {
        dim3 ga(NQT, 32);
        attn_mma_kernel<<<ga, 128>>>(QH, KH, VH, OH);
    }
    {
        dim3 g(NTOK / 128, 2, 4);
        hgemm_kernel<<<g, 256>>>(W16 + 212992, OH, nullptr, nullptr, O2, O2h, 0);
        hgemm_kernel<<<g, 256>>>(W16 + 278528, O2h, b1, nullptr, nullptr, H1h, 1);
        hgemm_kernel<<<g, 256>>>(W16 + 344064, H1h, b2, O2, PRE, nullptr, 0);
    }
    bnstats_kernel<<<256, 256>>>(PRE, gamma, beta);
    bnapply_kernel<<<(589824 + 255) / 256, 256>>>(PRE, out);
}

// round 11
// speedup vs baseline: 11.2796x; 1.1174x over previous
#include <cuda_runtime.h>
#include <cuda_fp16.h>
#include <math.h>

#define NTOK 2304
#define HWDIM 48
#define FEATC 256
#define NKT 36
#define NQT 18

typedef unsigned long long ull;
typedef unsigned int u32;

__device__ float g_scratch[17763840];
__device__ float g_scale[256];
__device__ float g_shift[256];

__device__ __forceinline__ u32 f16pack(float lo, float hi) {
    u32 r;
    asm("cvt.rn.f16x2.f32 %0, %1, %2;" : "=r"(r) : "f"(hi), "f"(lo));
    return r;
}
__device__ __forceinline__ u32 ex2h2(u32 x) {
    u32 r;
    asm("ex2.approx.f16x2 %0, %1;" : "=r"(r) : "r"(x));
    return r;
}
__device__ __forceinline__ void mma16816(float* d, u32 a0, u32 a1, u32 a2, u32 a3,
                                         u32 b0, u32 b1) {
    asm volatile(
        "mma.sync.aligned.m16n8k16.row.col.f32.f16.f16.f32 "
        "{%0,%1,%2,%3},{%4,%5,%6,%7},{%8,%9},{%0,%1,%2,%3};"
        : "+f"(d[0]), "+f"(d[1]), "+f"(d[2]), "+f"(d[3])
        : "r"(a0), "r"(a1), "r"(a2), "r"(a3), "r"(b0), "r"(b1));
}
__device__ __forceinline__ u32 smem_u32(const void* p) {
    u32 a;
    asm("{ .reg .u64 t; cvta.to.shared.u64 t, %1; cvt.u32.u64 %0, t; }" : "=r"(a) : "l"(p));
    return a;
}
#define CP16(dst, src) asm volatile("cp.async.ca.shared.global [%0], [%1], 16;" :: "r"(dst), "l"(src))
#define CP_COMMIT()    asm volatile("cp.async.commit_group;" ::: "memory")
#define CP_WAIT0()     asm volatile("cp.async.wait_group 0;" ::: "memory")
#define CP_WAIT1()     asm volatile("cp.async.wait_group 1;" ::: "memory")

// ================= PE -> fp16 channels appended to XIN q/k slices =================
__global__ void pe16_kernel(__half* __restrict__ XIN) {
    int idx = blockIdx.x * 256 + threadIdx.x;
    if (idx >= 32 * NTOK) return;
    int tok = idx >> 5, c = idx & 31;
    float val = 0.f;
    if (c < 30) {
        int i = tok / HWDIM, j = tok % HWDIM;
        const float SC = 6.283185307179586f;
        int axis = c / 10, t = c % 10;
        float e;
        if (axis == 0)      e = (float)(i + 1) / (HWDIM + 1e-6f) * SC;
        else if (axis == 1) e = (float)(j + 1) / (HWDIM + 1e-6f) * SC;
        else                e = SC;
        float freq = powf(10000.0f, (2.0f * (float)(t >> 1)) / 10.0f);
        float ph = e / freq;
        val = (t & 1) ? cosf(ph) : sinf(ph);
    }
    __half h = __float2half_rn(val);
#pragma unroll
    for (int s = 0; s < 8; s++)
        XIN[(size_t)s * 663552 + (size_t)tok * 288 + 256 + c] = h;
}

// ================= weight conversion =================
__global__ void wconv_kernel(const float* __restrict__ wq, const float* __restrict__ wk,
                             const float* __restrict__ wv, const float* __restrict__ wfc,
                             const float* __restrict__ w1, const float* __restrict__ w2,
                             __half* __restrict__ W16) {
    int idx = blockIdx.x * 256 + threadIdx.x;
    if (idx >= 409600) return;
    float v;
    if (idx < 147456) {
        int w = idx / 73728;
        int rem = idx - w * 73728;
        int r = rem / 288, c = rem - r * 288;
        const float* src = w ? wk : wq;
        v = (c < 286) ? src[(size_t)r * 286 + c] : 0.f;
    } else {
        int idx2 = idx - 147456;
        int w = idx2 >> 16, r = (idx2 >> 8) & 255, c = idx2 & 255;
        const float* src = (w == 0) ? wv : (w == 1) ? wfc : (w == 2) ? w1 : w2;
        v = src[(size_t)r * 256 + c];
    }
    W16[idx] = __float2half_rn(v);
}

// ================= input transpose+convert =================
__global__ void __launch_bounds__(256) xconv_kernel(const float* __restrict__ q,
                                                    const float* __restrict__ k,
                                                    const float* __restrict__ v,
                                                    __half* __restrict__ XIN) {
    __shared__ float tile[32][132];
    int z = blockIdx.z;
    int op = z >> 2, b = z & 3;
    const float* src = (op == 0 ? q : op == 1 ? k : v) + (size_t)b * FEATC * NTOK;
    int ldx = (op == 2) ? 256 : 288;
    __half* dst = XIN + (op == 2 ? (size_t)8 * 663552 + (size_t)b * 589824
                                 : (size_t)(op * 4 + b) * 663552);
    int t0 = blockIdx.x * 128, c0 = blockIdx.y * 32;
    int tid = threadIdx.x;
#pragma unroll
    for (int j = 0; j < 4; j++) {
        int i = tid + j * 256;
        int row = i >> 5, f4 = i & 31;
        float4 vv = *(const float4*)(src + (size_t)(c0 + row) * NTOK + t0 + f4 * 4);
        tile[row][f4 * 4] = vv.x;
        tile[row][f4 * 4 + 1] = vv.y;
        tile[row][f4 * 4 + 2] = vv.z;
        tile[row][f4 * 4 + 3] = vv.w;
    }
    __syncthreads();
#pragma unroll
    for (int j = 0; j < 2; j++) {
        int i = tid + j * 256;
        int tok = i >> 2, q4 = i & 3;
        u32 out4[4];
#pragma unroll
        for (int p = 0; p < 4; p++) {
            int c = q4 * 8 + p * 2;
            out4[p] = f16pack(tile[c][tok], tile[c + 1][tok]);
        }
        *(uint4*)(dst + (size_t)(t0 + tok) * ldx + c0 + q4 * 8) = *(uint4*)out4;
    }
}

// ================= HMMA GEMM body: cp.async double-buffered =================
// smem: stage s at [s*20480, s*20480+10240)=W, [+10240,+20480)=X; epilogue sT overlays.
__device__ __forceinline__ void hgemm_body(const __half* __restrict__ W16, int kdim,
                                           const __half* __restrict__ XH, int ldx,
                                           const float* __restrict__ bVec,
                                           const float* __restrict__ resid,
                                           float qscale, int relu,
                                           float* __restrict__ outF,
                                           __half* __restrict__ outTok,
                                           __half* __restrict__ outC,
                                           unsigned char* smem) {
    int tid = threadIdx.x, wid = tid >> 5, lane = tid & 31;
    int wr = wid >> 2, wc = wid & 3;
    int oc0 = blockIdx.y * 128, t0 = blockIdx.x * 128;
    u32 sbase = smem_u32(smem);
    int nsteps = kdim >> 5;

    float acc[4][4][4];
#pragma unroll
    for (int m = 0; m < 4; m++)
#pragma unroll
        for (int n = 0; n < 4; n++)
#pragma unroll
            for (int c = 0; c < 4; c++) acc[m][n][c] = 0.f;

    // prologue: stage 0
    {
#pragma unroll
        for (int i = 0; i < 2; i++) {
            int idx = tid + i * 256;
            int row = idx >> 2, ch = idx & 3;
            CP16(sbase + row * 80 + ch * 16, W16 + (size_t)(oc0 + row) * kdim + ch * 8);
            CP16(sbase + 10240 + row * 80 + ch * 16, XH + (size_t)(t0 + row) * ldx + ch * 8);
        }
        CP_COMMIT();
    }

    for (int s = 0; s < nsteps; s++) {
        if (s + 1 < nsteps) {
            int kk = (s + 1) << 5;
            u32 sb = sbase + ((s + 1) & 1) * 20480;
#pragma unroll
            for (int i = 0; i < 2; i++) {
                int idx = tid + i * 256;
                int row = idx >> 2, ch = idx & 3;
                CP16(sb + row * 80 + ch * 16, W16 + (size_t)(oc0 + row) * kdim + kk + ch * 8);
                CP16(sb + 10240 + row * 80 + ch * 16, XH + (size_t)(t0 + row) * ldx + kk + ch * 8);
            }
            CP_COMMIT();
            CP_WAIT1();
        } else {
            CP_WAIT0();
        }
        __syncthreads();
        __half (*sW)[40] = (__half(*)[40])(smem + (s & 1) * 20480);
        __half (*sX)[40] = (__half(*)[40])(smem + (s & 1) * 20480 + 10240);
#pragma unroll
        for (int ks = 0; ks < 2; ks++) {
            int cb = ks * 16 + (lane & 3) * 2;
            u32 a[4][4], bfr[4][2];
#pragma unroll
            for (int m = 0; m < 4; m++) {
                int r = wr * 64 + m * 16 + (lane >> 2);
                a[m][0] = *(u32*)&sW[r][cb];
                a[m][1] = *(u32*)&sW[r + 8][cb];
                a[m][2] = *(u32*)&sW[r][cb + 8];
                a[m][3] = *(u32*)&sW[r + 8][cb + 8];
            }
#pragma unroll
            for (int n = 0; n < 4; n++) {
                int key = wc * 32 + n * 8 + (lane >> 2);
                bfr[n][0] = *(u32*)&sX[key][cb];
                bfr[n][1] = *(u32*)&sX[key][cb + 8];
            }
#pragma unroll
            for (int m = 0; m < 4; m++)
#pragma unroll
                for (int n = 0; n < 4; n++)
                    mma16816(acc[m][n], a[m][0], a[m][1], a[m][2], a[m][3], bfr[n][0], bfr[n][1]);
        }
        __syncthreads();
    }

#pragma unroll
    for (int m = 0; m < 4; m++) {
#pragma unroll
        for (int n = 0; n < 4; n++) {
            int r0 = oc0 + wr * 64 + m * 16 + (lane >> 2);
            int r1 = r0 + 8;
            int cX = t0 + wc * 32 + n * 8 + (lane & 3) * 2;
            float v00 = acc[m][n][0], v01 = acc[m][n][1];
            float v10 = acc[m][n][2], v11 = acc[m][n][3];
            if (bVec) {
                float bv0 = bVec[r0], bv1 = bVec[r1];
                v00 += bv0; v01 += bv0; v10 += bv1; v11 += bv1;
            }
            if (relu) {
                v00 = fmaxf(v00, 0.f); v01 = fmaxf(v01, 0.f);
                v10 = fmaxf(v10, 0.f); v11 = fmaxf(v11, 0.f);
            }
            if (resid) {
                v00 += resid[(size_t)r0 * NTOK + cX];
                v01 += resid[(size_t)r0 * NTOK + cX + 1];
                v10 += resid[(size_t)r1 * NTOK + cX];
                v11 += resid[(size_t)r1 * NTOK + cX + 1];
            }
            v00 *= qscale; v01 *= qscale; v10 *= qscale; v11 *= qscale;
            acc[m][n][0] = v00; acc[m][n][1] = v01; acc[m][n][2] = v10; acc[m][n][3] = v11;
            if (outF) {
                *(float2*)(outF + (size_t)r0 * NTOK + cX) = make_float2(v00, v01);
                *(float2*)(outF + (size_t)r1 * NTOK + cX) = make_float2(v10, v11);
            }
            if (outC) {
                *(u32*)(outC + (size_t)r0 * NTOK + cX) = f16pack(v00, v01);
                *(u32*)(outC + (size_t)r1 * NTOK + cX) = f16pack(v10, v11);
            }
        }
    }
    if (outTok) {
        __half (*sT)[136] = (__half(*)[136])smem;
        __syncthreads();
#pragma unroll
        for (int m = 0; m < 4; m++)
#pragma unroll
            for (int n = 0; n < 4; n++) {
                int lr0 = wr * 64 + m * 16 + (lane >> 2);
                int lc = wc * 32 + n * 8 + (lane & 3) * 2;
                sT[lc][lr0]     = __float2half_rn(acc[m][n][0]);
                sT[lc + 1][lr0] = __float2half_rn(acc[m][n][1]);
                sT[lc][lr0 + 8]     = __float2half_rn(acc[m][n][2]);
                sT[lc + 1][lr0 + 8] = __float2half_rn(acc[m][n][3]);
            }
        __syncthreads();
#pragma unroll
        for (int i = 0; i < 8; i++) {
            int idx = tid + i * 256;
            int row = idx >> 4, ch = idx & 15;
            *(uint4*)(outTok + (size_t)(t0 + row) * 256 + oc0 + ch * 8) =
                *(uint4*)&sT[row][ch * 8];
        }
    }
}

// proj: z = op*4 + b
__global__ void __launch_bounds__(256) proj_h_kernel(const __half* __restrict__ W16,
                                                     const __half* __restrict__ XIN,
                                                     __half* __restrict__ QH,
                                                     __half* __restrict__ KH,
                                                     __half* __restrict__ VH) {
    __shared__ __align__(16) unsigned char smem[40960];
    int z = blockIdx.z;
    int op = z >> 2, b = z & 3;
    if (op == 0) {
        hgemm_body(W16, 288, XIN + (size_t)b * 663552, 288, nullptr, nullptr,
                   0.2550348634f, 0, nullptr, QH + (size_t)b * 589824, nullptr, smem);
    } else if (op == 1) {
        hgemm_body(W16 + 73728, 288, XIN + (size_t)(4 + b) * 663552, 288, nullptr, nullptr,
                   1.0f, 0, nullptr, KH + (size_t)b * 589824, nullptr, smem);
    } else {
        hgemm_body(W16 + 147456, 256, XIN + (size_t)8 * 663552 + (size_t)b * 589824, 256,
                   nullptr, nullptr, 1.0f, 0, nullptr, nullptr, VH + (size_t)b * 589824, smem);
    }
}

__global__ void __launch_bounds__(256) hgemm_kernel(const __half* __restrict__ W16,
                                                    const __half* __restrict__ XH,
                                                    const float* __restrict__ bVec,
                                                    const float* __restrict__ resid,
                                                    float* __restrict__ outF,
                                                    __half* __restrict__ outTok,
                                                    int relu) {
    __shared__ __align__(16) unsigned char smem[40960];
    size_t off = (size_t)blockIdx.z * 589824;
    hgemm_body(W16, 256, XH + off, 256, bVec, resid ? resid + off : nullptr, 1.0f, relu,
               outF ? outF + off : nullptr, outTok ? outTok + off : nullptr, nullptr, smem);
}

// ================= warp-MMA flash attention: cp.async double-buffered K/V =================
__global__ void __launch_bounds__(128) attn_mma_kernel(const __half* __restrict__ QH,
                                                       const __half* __restrict__ KH,
                                                       const __half* __restrict__ VH,
                                                       __half* __restrict__ OH) {
    __shared__ __half sQ[128][40];
    __shared__ __half sK[2][64][40];
    __shared__ __half sV[2][40][72];

    int tid = threadIdx.x, wid = tid >> 5, lane = tid & 31;
    int q0 = blockIdx.x * 128;
    int bh = blockIdx.y;
    int b = bh >> 3, h = bh & 7;
    u32 sKa = smem_u32(&sK[0][0][0]);
    u32 sVa = smem_u32(&sV[0][0][0]);

#pragma unroll
    for (int c = 0; c < 4; c++) {
        int i = tid + c * 128;
        int row = i >> 2, ch = i & 3;
        *(uint4*)&sQ[row][ch * 8] =
            *(const uint4*)(QH + ((size_t)b * NTOK + q0 + row) * 256 + h * 32 + ch * 8);
    }
    // V static rows (both stages): row 32 = ones, rows 33-39 = zero (cols<64 used)
#pragma unroll
    for (int st = 0; st < 2; st++) {
        if (tid < 32) ((u32*)&sV[st][32][0])[tid] = 0x3C003C00u;
        for (int i = tid; i < 252; i += 128) ((u32*)&sV[st][33][0])[i] = 0u;
    }
    __syncthreads();

    u32 qa[2][2][4];
#pragma unroll
    for (int m = 0; m < 2; m++)
#pragma unroll
        for (int ks = 0; ks < 2; ks++) {
            int r = wid * 32 + m * 16 + (lane >> 2);
            int cb = ks * 16 + (lane & 3) * 2;
            qa[m][ks][0] = *(u32*)&sQ[r][cb];
            qa[m][ks][1] = *(u32*)&sQ[r + 8][cb];
            qa[m][ks][2] = *(u32*)&sQ[r][cb + 8];
            qa[m][ks][3] = *(u32*)&sQ[r + 8][cb + 8];
        }

    // prologue: stage 0 loads (kb = 0)
    {
#pragma unroll
        for (int i = 0; i < 2; i++) {
            int idx = tid + i * 128;
            int row = idx >> 2, ch = idx & 3;
            CP16(sKa + row * 80 + ch * 16,
                 KH + ((size_t)b * NTOK + row) * 256 + h * 32 + ch * 8);
        }
#pragma unroll
        for (int i = 0; i < 2; i++) {
            int idx = tid + i * 128;
            int row = idx >> 3, ch = idx & 7;
            CP16(sVa + row * 144 + ch * 16,
                 VH + ((size_t)(b * 256 + h * 32 + row)) * NTOK + ch * 8);
        }
        CP_COMMIT();
    }

    float Oa[2][5][4];
#pragma unroll
    for (int m = 0; m < 2; m++)
#pragma unroll
        for (int n = 0; n < 5; n++)
#pragma unroll
            for (int c = 0; c < 4; c++) Oa[m][n][c] = 0.f;

#pragma unroll 1
    for (int kt = 0; kt < NKT; kt++) {
        if (kt + 1 < NKT) {
            int kb = (kt + 1) * 64;
            u32 kdst = sKa + ((kt + 1) & 1) * 5120;
            u32 vdst = sVa + ((kt + 1) & 1) * 5760;
#pragma unroll
            for (int i = 0; i < 2; i++) {
                int idx = tid + i * 128;
                int row = idx >> 2, ch = idx & 3;
                CP16(kdst + row * 80 + ch * 16,
                     KH + ((size_t)b * NTOK + kb + row) * 256 + h * 32 + ch * 8);
            }
#pragma unroll
            for (int i = 0; i < 2; i++) {
                int idx = tid + i * 128;
                int row = idx >> 3, ch = idx & 7;
                CP16(vdst + row * 144 + ch * 16,
                     VH + ((size_t)(b * 256 + h * 32 + row)) * NTOK + kb + ch * 8);
            }
            CP_COMMIT();
            CP_WAIT1();
        } else {
            CP_WAIT0();
        }
        __syncthreads();
        int st = kt & 1;

        float S[2][8][4];
#pragma unroll
        for (int m = 0; m < 2; m++)
#pragma unroll
            for (int n = 0; n < 8; n++)
#pragma unroll
                for (int c = 0; c < 4; c++) S[m][n][c] = 0.f;

#pragma unroll
        for (int nb = 0; nb < 8; nb++) {
            int key = nb * 8 + (lane >> 2);
#pragma unroll
            for (int ks = 0; ks < 2; ks++) {
                u32 b0 = *(u32*)&sK[st][key][ks * 16 + (lane & 3) * 2];
                u32 b1 = *(u32*)&sK[st][key][ks * 16 + 8 + (lane & 3) * 2];
                mma16816(S[0][nb], qa[0][ks][0], qa[0][ks][1], qa[0][ks][2], qa[0][ks][3], b0, b1);
                mma16816(S[1][nb], qa[1][ks][0], qa[1][ks][1], qa[1][ks][2], qa[1][ks][3], b0, b1);
            }
        }

        u32 P[2][8][2];
#pragma unroll
        for (int m = 0; m < 2; m++)
#pragma unroll
            for (int nb = 0; nb < 8; nb++) {
                P[m][nb][0] = ex2h2(f16pack(S[m][nb][0], S[m][nb][1]));
                P[m][nb][1] = ex2h2(f16pack(S[m][nb][2], S[m][nb][3]));
            }

#pragma unroll
        for (int nb5 = 0; nb5 < 5; nb5++) {
            int d = nb5 * 8 + (lane >> 2);
#pragma unroll
            for (int ks = 0; ks < 4; ks++) {
                u32 vb0 = *(u32*)&sV[st][d][ks * 16 + (lane & 3) * 2];
                u32 vb1 = *(u32*)&sV[st][d][ks * 16 + 8 + (lane & 3) * 2];
                mma16816(Oa[0][nb5], P[0][2 * ks][0], P[0][2 * ks][1],
                         P[0][2 * ks + 1][0], P[0][2 * ks + 1][1], vb0, vb1);
                mma16816(Oa[1][nb5], P[1][2 * ks][0], P[1][2 * ks][1],
                         P[1][2 * ks + 1][0], P[1][2 * ks + 1][1], vb0, vb1);
            }
        }
        __syncthreads();
    }

    int qb = q0 + wid * 32;
#pragma unroll
    for (int m = 0; m < 2; m++) {
        float li0 = 1.f / __shfl_sync(0xffffffffu, Oa[m][4][0], lane & ~3);
        float li1 = 1.f / __shfl_sync(0xffffffffu, Oa[m][4][2], lane & ~3);
        int r0 = qb + m * 16 + (lane >> 2);
#pragma unroll
        for (int nb = 0; nb < 4; nb++) {
            int d = nb * 8 + (lane & 3) * 2;
            *(u32*)(OH + ((size_t)b * NTOK + r0) * 256 + h * 32 + d) =
                f16pack(Oa[m][nb][0] * li0, Oa[m][nb][1] * li0);
            *(u32*)(OH + ((size_t)b * NTOK + r0 + 8) * 256 + h * 32 + d) =
                f16pack(Oa[m][nb][2] * li1, Oa[m][nb][3] * li1);
        }
    }
}

// ================= BN =================
__global__ void bnstats_kernel(const float* __restrict__ pre,
                               const float* __restrict__ gamma,
                               const float* __restrict__ beta) {
    int c = blockIdx.x;
    float s = 0.f, s2 = 0.f;
    for (int b = 0; b < 4; b++) {
        const float* p = pre + ((size_t)b * FEATC + c) * NTOK;
        for (int i = threadIdx.x; i < NTOK / 4; i += 256) {
            float4 v = ((const float4*)p)[i];
            s += v.x + v.y + v.z + v.w;
            s2 += v.x * v.x + v.y * v.y + v.z * v.z + v.w * v.w;
        }
    }
    __shared__ float sh0[256], sh1[256];
    sh0[threadIdx.x] = s;
    sh1[threadIdx.x] = s2;
    __syncthreads();
    for (int st = 128; st > 0; st >>= 1) {
        if (threadIdx.x < st) {
            sh0[threadIdx.x] += sh0[threadIdx.x + st];
            sh1[threadIdx.x] += sh1[threadIdx.x + st];
        }
        __syncthreads();
    }
    if (threadIdx.x == 0) {
        const float n = 4.0f * NTOK;
        float mean = sh0[0] / n;
        float var = sh1[0] / n - mean * mean;
        float is = rsqrtf(var + 1e-5f);
        float scl = gamma[c] * is;
        g_scale[c] = scl;
        g_shift[c] = beta[c] - mean * scl;
    }
}

__global__ void bnapply_kernel(const float* __restrict__ pre, float* __restrict__ out) {
    int idx = blockIdx.x * 256 + threadIdx.x;   // float4 index
    if (idx >= 589824) return;
    int c = ((idx << 2) / NTOK) & 255;
    float sc = g_scale[c], sh = g_shift[c];
    float4 v = ((const float4*)pre)[idx];
    v.x = v.x * sc + sh; v.y = v.y * sc + sh;
    v.z = v.z * sc + sh; v.w = v.w * sc + sh;
    ((float4*)out)[idx] = v;
}

// ================= launch =================
extern "C" void kernel_launch(void* const* d_in, const int* in_sizes, int n_in,
                              void* d_out, int out_size) {
    const float* q     = (const float*)d_in[0];
    const float* k     = (const float*)d_in[1];
    const float* v     = (const float*)d_in[2];
    const float* wq    = (const float*)d_in[3];
    const float* wk    = (const float*)d_in[4];
    const float* wv    = (const float*)d_in[5];
    const float* wfc   = (const float*)d_in[6];
    const float* w1    = (const float*)d_in[7];
    const float* b1    = (const float*)d_in[8];
    const float* w2    = (const float*)d_in[9];
    const float* b2    = (const float*)d_in[10];
    const float* gamma = (const float*)d_in[11];
    const float* beta  = (const float*)d_in[12];
    float* out = (float*)d_out;

    float* base = nullptr;
    cudaGetSymbolAddress((void**)&base, g_scratch);
    float* O2  = base;                  // 2359296
    float* PRE = base + 2359296;        // 2359296
    __half* hb  = (__half*)(base + 4718592);
    __half* W16 = hb;                   // 409600
    __half* XIN = hb + 409600;          // 7667712
    __half* QH  = hb + 8077312;         // 2359296 each
    __half* KH  = QH + 2359296;
    __half* VH  = KH + 2359296;
    __half* OH  = VH + 2359296;
    __half* O2h = OH + 2359296;
    __half* H1h = O2h + 2359296;

    pe16_kernel<<<(32 * NTOK + 255) / 256, 256>>>(XIN);
    wconv_kernel<<<1600, 256>>>(wq, wk, wv, wfc, w1, w2, W16);
    {
        dim3 g(NTOK / 128, FEATC / 32, 12);
        xconv_kernel<<<g, 256>>>(q, k, v, XIN);
    }
    {
        dim3 g(NTOK / 128, 2, 12);
        proj_h_kernel<<<g, 256>>>(W16, XIN, QH, KH, VH);
    }
    {
        dim3 ga(NQT, 32);
        attn_mma_kernel<<<ga, 128>>>(QH, KH, VH, OH);
    }
    {
        dim3 g(NTOK / 128, 2, 4);
        hgemm_kernel<<<g, 256>>>(W16 + 212992, OH, nullptr, nullptr, O2, O2h, 0);
        hgemm_kernel<<<g, 256>>>(W16 + 278528, O2h, b1, nullptr, nullptr, H1h, 1);
        hgemm_kernel<<<g, 256>>>(W16 + 344064, H1h, b2, O2, PRE, nullptr, 0);
    }
    bnstats_kernel<<<256, 256>>>(PRE, gamma, beta);
    bnapply_kernel<<<(589824 + 255) / 256, 256>>>(PRE, out);
}

// round 12
// speedup vs baseline: 11.8409x; 1.0498x over previous
#include <cuda_runtime.h>
#include <cuda_fp16.h>
#include <math.h>

#define NTOK 2304
#define HWDIM 48
#define FEATC 256
#define NKT 36
#define NQT 18

typedef unsigned long long ull;
typedef unsigned int u32;

__device__ float g_scratch[17763840];
__device__ float g_scale[256];
__device__ float g_shift[256];

__device__ __forceinline__ u32 f16pack(float lo, float hi) {
    u32 r;
    asm("cvt.rn.f16x2.f32 %0, %1, %2;" : "=r"(r) : "f"(hi), "f"(lo));
    return r;
}
__device__ __forceinline__ u32 ex2h2(u32 x) {
    u32 r;
    asm("ex2.approx.f16x2 %0, %1;" : "=r"(r) : "r"(x));
    return r;
}
__device__ __forceinline__ void mma16816(float* d, u32 a0, u32 a1, u32 a2, u32 a3,
                                         u32 b0, u32 b1) {
    asm volatile(
        "mma.sync.aligned.m16n8k16.row.col.f32.f16.f16.f32 "
        "{%0,%1,%2,%3},{%4,%5,%6,%7},{%8,%9},{%0,%1,%2,%3};"
        : "+f"(d[0]), "+f"(d[1]), "+f"(d[2]), "+f"(d[3])
        : "r"(a0), "r"(a1), "r"(a2), "r"(a3), "r"(b0), "r"(b1));
}
__device__ __forceinline__ u32 smem_u32(const void* p) {
    u32 a;
    asm("{ .reg .u64 t; cvta.to.shared.u64 t, %1; cvt.u32.u64 %0, t; }" : "=r"(a) : "l"(p));
    return a;
}
__device__ __forceinline__ void ldsm4(u32* r, u32 addr) {
    asm volatile("ldmatrix.sync.aligned.m8n8.x4.shared.b16 {%0,%1,%2,%3}, [%4];"
                 : "=r"(r[0]), "=r"(r[1]), "=r"(r[2]), "=r"(r[3]) : "r"(addr));
}
__device__ __forceinline__ void ldsm2(u32* r, u32 addr) {
    asm volatile("ldmatrix.sync.aligned.m8n8.x2.shared.b16 {%0,%1}, [%2];"
                 : "=r"(r[0]), "=r"(r[1]) : "r"(addr));
}
#define CP16(dst, src) asm volatile("cp.async.ca.shared.global [%0], [%1], 16;" :: "r"(dst), "l"(src))
#define CP_COMMIT()    asm volatile("cp.async.commit_group;" ::: "memory")
#define CP_WAIT0()     asm volatile("cp.async.wait_group 0;" ::: "memory")
#define CP_WAIT1()     asm volatile("cp.async.wait_group 1;" ::: "memory")

// ================= PE -> fp16 channels appended to XIN q/k slices =================
__global__ void pe16_kernel(__half* __restrict__ XIN) {
    int idx = blockIdx.x * 256 + threadIdx.x;
    if (idx >= 32 * NTOK) return;
    int tok = idx >> 5, c = idx & 31;
    float val = 0.f;
    if (c < 30) {
        int i = tok / HWDIM, j = tok % HWDIM;
        const float SC = 6.283185307179586f;
        int axis = c / 10, t = c % 10;
        float e;
        if (axis == 0)      e = (float)(i + 1) / (HWDIM + 1e-6f) * SC;
        else if (axis == 1) e = (float)(j + 1) / (HWDIM + 1e-6f) * SC;
        else                e = SC;
        float freq = powf(10000.0f, (2.0f * (float)(t >> 1)) / 10.0f);
        float ph = e / freq;
        val = (t & 1) ? cosf(ph) : sinf(ph);
    }
    __half h = __float2half_rn(val);
#pragma unroll
    for (int s = 0; s < 8; s++)
        XIN[(size_t)s * 663552 + (size_t)tok * 288 + 256 + c] = h;
}

// ================= weight conversion =================
__global__ void wconv_kernel(const float* __restrict__ wq, const float* __restrict__ wk,
                             const float* __restrict__ wv, const float* __restrict__ wfc,
                             const float* __restrict__ w1, const float* __restrict__ w2,
                             __half* __restrict__ W16) {
    int idx = blockIdx.x * 256 + threadIdx.x;
    if (idx >= 409600) return;
    float v;
    if (idx < 147456) {
        int w = idx / 73728;
        int rem = idx - w * 73728;
        int r = rem / 288, c = rem - r * 288;
        const float* src = w ? wk : wq;
        v = (c < 286) ? src[(size_t)r * 286 + c] : 0.f;
    } else {
        int idx2 = idx - 147456;
        int w = idx2 >> 16, r = (idx2 >> 8) & 255, c = idx2 & 255;
        const float* src = (w == 0) ? wv : (w == 1) ? wfc : (w == 2) ? w1 : w2;
        v = src[(size_t)r * 256 + c];
    }
    W16[idx] = __float2half_rn(v);
}

// ================= input transpose+convert =================
__global__ void __launch_bounds__(256) xconv_kernel(const float* __restrict__ q,
                                                    const float* __restrict__ k,
                                                    const float* __restrict__ v,
                                                    __half* __restrict__ XIN) {
    __shared__ float tile[32][132];
    int z = blockIdx.z;
    int op = z >> 2, b = z & 3;
    const float* src = (op == 0 ? q : op == 1 ? k : v) + (size_t)b * FEATC * NTOK;
    int ldx = (op == 2) ? 256 : 288;
    __half* dst = XIN + (op == 2 ? (size_t)8 * 663552 + (size_t)b * 589824
                                 : (size_t)(op * 4 + b) * 663552);
    int t0 = blockIdx.x * 128, c0 = blockIdx.y * 32;
    int tid = threadIdx.x;
#pragma unroll
    for (int j = 0; j < 4; j++) {
        int i = tid + j * 256;
        int row = i >> 5, f4 = i & 31;
        float4 vv = *(const float4*)(src + (size_t)(c0 + row) * NTOK + t0 + f4 * 4);
        tile[row][f4 * 4] = vv.x;
        tile[row][f4 * 4 + 1] = vv.y;
        tile[row][f4 * 4 + 2] = vv.z;
        tile[row][f4 * 4 + 3] = vv.w;
    }
    __syncthreads();
#pragma unroll
    for (int j = 0; j < 2; j++) {
        int i = tid + j * 256;
        int tok = i >> 2, q4 = i & 3;
        u32 out4[4];
#pragma unroll
        for (int p = 0; p < 4; p++) {
            int c = q4 * 8 + p * 2;
            out4[p] = f16pack(tile[c][tok], tile[c + 1][tok]);
        }
        *(uint4*)(dst + (size_t)(t0 + tok) * ldx + c0 + q4 * 8) = *(uint4*)out4;
    }
}

// ================= HMMA GEMM body: cp.async double-buffered + ldmatrix =================
__device__ __forceinline__ void hgemm_body(const __half* __restrict__ W16, int kdim,
                                           const __half* __restrict__ XH, int ldx,
                                           const float* __restrict__ bVec,
                                           const float* __restrict__ resid,
                                           float qscale, int relu,
                                           float* __restrict__ outF,
                                           __half* __restrict__ outTok,
                                           __half* __restrict__ outC,
                                           unsigned char* smem) {
    int tid = threadIdx.x, wid = tid >> 5, lane = tid & 31;
    int wr = wid >> 2, wc = wid & 3;
    int oc0 = blockIdx.y * 128, t0 = blockIdx.x * 128;
    u32 sbase = smem_u32(smem);
    int nsteps = kdim >> 5;

    float acc[4][4][4];
#pragma unroll
    for (int m = 0; m < 4; m++)
#pragma unroll
        for (int n = 0; n < 4; n++)
#pragma unroll
            for (int c = 0; c < 4; c++) acc[m][n][c] = 0.f;

    {
#pragma unroll
        for (int i = 0; i < 2; i++) {
            int idx = tid + i * 256;
            int row = idx >> 2, ch = idx & 3;
            CP16(sbase + row * 80 + ch * 16, W16 + (size_t)(oc0 + row) * kdim + ch * 8);
            CP16(sbase + 10240 + row * 80 + ch * 16, XH + (size_t)(t0 + row) * ldx + ch * 8);
        }
        CP_COMMIT();
    }

    for (int s = 0; s < nsteps; s++) {
        if (s + 1 < nsteps) {
            int kk = (s + 1) << 5;
            u32 sb = sbase + ((s + 1) & 1) * 20480;
#pragma unroll
            for (int i = 0; i < 2; i++) {
                int idx = tid + i * 256;
                int row = idx >> 2, ch = idx & 3;
                CP16(sb + row * 80 + ch * 16, W16 + (size_t)(oc0 + row) * kdim + kk + ch * 8);
                CP16(sb + 10240 + row * 80 + ch * 16, XH + (size_t)(t0 + row) * ldx + kk + ch * 8);
            }
            CP_COMMIT();
            CP_WAIT1();
        } else {
            CP_WAIT0();
        }
        __syncthreads();
        u32 sWst = sbase + (s & 1) * 20480;
        u32 sXst = sWst + 10240;
#pragma unroll
        for (int ks = 0; ks < 2; ks++) {
            int cb0 = ks * 16;
            u32 a[4][4], bfr[4][2];
#pragma unroll
            for (int m = 0; m < 4; m++) {
                int row = wr * 64 + m * 16 + (lane & 15);
                int col = cb0 + (lane >> 4) * 8;
                ldsm4(a[m], sWst + row * 80 + col * 2);
            }
#pragma unroll
            for (int p = 0; p < 2; p++) {
                u32 t[4];
                int row = wc * 32 + p * 16 + ((lane >> 4) & 1) * 8 + (lane & 7);
                int col = cb0 + ((lane >> 3) & 1) * 8;
                ldsm4(t, sXst + row * 80 + col * 2);
                bfr[2 * p][0] = t[0]; bfr[2 * p][1] = t[1];
                bfr[2 * p + 1][0] = t[2]; bfr[2 * p + 1][1] = t[3];
            }
#pragma unroll
            for (int m = 0; m < 4; m++)
#pragma unroll
                for (int n = 0; n < 4; n++)
                    mma16816(acc[m][n], a[m][0], a[m][1], a[m][2], a[m][3], bfr[n][0], bfr[n][1]);
        }
        __syncthreads();
    }

#pragma unroll
    for (int m = 0; m < 4; m++) {
#pragma unroll
        for (int n = 0; n < 4; n++) {
            int r0 = oc0 + wr * 64 + m * 16 + (lane >> 2);
            int r1 = r0 + 8;
            int cX = t0 + wc * 32 + n * 8 + (lane & 3) * 2;
            float v00 = acc[m][n][0], v01 = acc[m][n][1];
            float v10 = acc[m][n][2], v11 = acc[m][n][3];
            if (bVec) {
                float bv0 = bVec[r0], bv1 = bVec[r1];
                v00 += bv0; v01 += bv0; v10 += bv1; v11 += bv1;
            }
            if (relu) {
                v00 = fmaxf(v00, 0.f); v01 = fmaxf(v01, 0.f);
                v10 = fmaxf(v10, 0.f); v11 = fmaxf(v11, 0.f);
            }
            if (resid) {
                v00 += resid[(size_t)r0 * NTOK + cX];
                v01 += resid[(size_t)r0 * NTOK + cX + 1];
                v10 += resid[(size_t)r1 * NTOK + cX];
                v11 += resid[(size_t)r1 * NTOK + cX + 1];
            }
            v00 *= qscale; v01 *= qscale; v10 *= qscale; v11 *= qscale;
            acc[m][n][0] = v00; acc[m][n][1] = v01; acc[m][n][2] = v10; acc[m][n][3] = v11;
            if (outF) {
                *(float2*)(outF + (size_t)r0 * NTOK + cX) = make_float2(v00, v01);
                *(float2*)(outF + (size_t)r1 * NTOK + cX) = make_float2(v10, v11);
            }
            if (outC) {
                *(u32*)(outC + (size_t)r0 * NTOK + cX) = f16pack(v00, v01);
                *(u32*)(outC + (size_t)r1 * NTOK + cX) = f16pack(v10, v11);
            }
        }
    }
    if (outTok) {
        __half (*sT)[136] = (__half(*)[136])smem;
        __syncthreads();
#pragma unroll
        for (int m = 0; m < 4; m++)
#pragma unroll
            for (int n = 0; n < 4; n++) {
                int lr0 = wr * 64 + m * 16 + (lane >> 2);
                int lc = wc * 32 + n * 8 + (lane & 3) * 2;
                sT[lc][lr0]     = __float2half_rn(acc[m][n][0]);
                sT[lc + 1][lr0] = __float2half_rn(acc[m][n][1]);
                sT[lc][lr0 + 8]     = __float2half_rn(acc[m][n][2]);
                sT[lc + 1][lr0 + 8] = __float2half_rn(acc[m][n][3]);
            }
        __syncthreads();
#pragma unroll
        for (int i = 0; i < 8; i++) {
            int idx = tid + i * 256;
            int row = idx >> 4, ch = idx & 15;
            *(uint4*)(outTok + (size_t)(t0 + row) * 256 + oc0 + ch * 8) =
                *(uint4*)&sT[row][ch * 8];
        }
    }
}

// proj: z = op*4 + b
__global__ void __launch_bounds__(256) proj_h_kernel(const __half* __restrict__ W16,
                                                     const __half* __restrict__ XIN,
                                                     __half* __restrict__ QH,
                                                     __half* __restrict__ KH,
                                                     __half* __restrict__ VH) {
    __shared__ __align__(16) unsigned char smem[40960];
    int z = blockIdx.z;
    int op = z >> 2, b = z & 3;
    if (op == 0) {
        hgemm_body(W16, 288, XIN + (size_t)b * 663552, 288, nullptr, nullptr,
                   0.2550348634f, 0, nullptr, QH + (size_t)b * 589824, nullptr, smem);
    } else if (op == 1) {
        hgemm_body(W16 + 73728, 288, XIN + (size_t)(4 + b) * 663552, 288, nullptr, nullptr,
                   1.0f, 0, nullptr, KH + (size_t)b * 589824, nullptr, smem);
    } else {
        hgemm_body(W16 + 147456, 256, XIN + (size_t)8 * 663552 + (size_t)b * 589824, 256,
                   nullptr, nullptr, 1.0f, 0, nullptr, nullptr, VH + (size_t)b * 589824, smem);
    }
}

__global__ void __launch_bounds__(256) hgemm_kernel(const __half* __restrict__ W16,
                                                    const __half* __restrict__ XH,
                                                    const float* __restrict__ bVec,
                                                    const float* __restrict__ resid,
                                                    float* __restrict__ outF,
                                                    __half* __restrict__ outTok,
                                                    int relu) {
    __shared__ __align__(16) unsigned char smem[40960];
    size_t off = (size_t)blockIdx.z * 589824;
    hgemm_body(W16, 256, XH + off, 256, bVec, resid ? resid + off : nullptr, 1.0f, relu,
               outF ? outF + off : nullptr, outTok ? outTok + off : nullptr, nullptr, smem);
}

// ================= warp-MMA flash attention: cp.async + ldmatrix =================
__global__ void __launch_bounds__(128) attn_mma_kernel(const __half* __restrict__ QH,
                                                       const __half* __restrict__ KH,
                                                       const __half* __restrict__ VH,
                                                       __half* __restrict__ OH) {
    __shared__ __half sQ[128][40];
    __shared__ __half sK[2][64][40];
    __shared__ __half sV[2][40][72];

    int tid = threadIdx.x, wid = tid >> 5, lane = tid & 31;
    int q0 = blockIdx.x * 128;
    int bh = blockIdx.y;
    int b = bh >> 3, h = bh & 7;
    u32 sQa = smem_u32(&sQ[0][0]);
    u32 sKa = smem_u32(&sK[0][0][0]);
    u32 sVa = smem_u32(&sV[0][0][0]);

#pragma unroll
    for (int c = 0; c < 4; c++) {
        int i = tid + c * 128;
        int row = i >> 2, ch = i & 3;
        *(uint4*)&sQ[row][ch * 8] =
            *(const uint4*)(QH + ((size_t)b * NTOK + q0 + row) * 256 + h * 32 + ch * 8);
    }
#pragma unroll
    for (int st = 0; st < 2; st++) {
        if (tid < 32) ((u32*)&sV[st][32][0])[tid] = 0x3C003C00u;
        for (int i = tid; i < 252; i += 128) ((u32*)&sV[st][33][0])[i] = 0u;
    }
    // prologue: stage 0 K/V
    {
#pragma unroll
        for (int i = 0; i < 2; i++) {
            int idx = tid + i * 128;
            int row = idx >> 2, ch = idx & 3;
            CP16(sKa + row * 80 + ch * 16,
                 KH + ((size_t)b * NTOK + row) * 256 + h * 32 + ch * 8);
        }
#pragma unroll
        for (int i = 0; i < 2; i++) {
            int idx = tid + i * 128;
            int row = idx >> 3, ch = idx & 7;
            CP16(sVa + row * 144 + ch * 16,
                 VH + ((size_t)(b * 256 + h * 32 + row)) * NTOK + ch * 8);
        }
        CP_COMMIT();
    }
    __syncthreads();

    u32 qa[2][2][4];
#pragma unroll
    for (int m = 0; m < 2; m++)
#pragma unroll
        for (int ks = 0; ks < 2; ks++) {
            int row = wid * 32 + m * 16 + (lane & 15);
            int col = ks * 16 + (lane >> 4) * 8;
            ldsm4(qa[m][ks], sQa + row * 80 + col * 2);
        }

    float Oa[2][5][4];
#pragma unroll
    for (int m = 0; m < 2; m++)
#pragma unroll
        for (int n = 0; n < 5; n++)
#pragma unroll
            for (int c = 0; c < 4; c++) Oa[m][n][c] = 0.f;

#pragma unroll 1
    for (int kt = 0; kt < NKT; kt++) {
        if (kt + 1 < NKT) {
            int kb = (kt + 1) * 64;
            u32 kdst = sKa + ((kt + 1) & 1) * 5120;
            u32 vdst = sVa + ((kt + 1) & 1) * 5760;
#pragma unroll
            for (int i = 0; i < 2; i++) {
                int idx = tid + i * 128;
                int row = idx >> 2, ch = idx & 3;
                CP16(kdst + row * 80 + ch * 16,
                     KH + ((size_t)b * NTOK + kb + row) * 256 + h * 32 + ch * 8);
            }
#pragma unroll
            for (int i = 0; i < 2; i++) {
                int idx = tid + i * 128;
                int row = idx >> 3, ch = idx & 7;
                CP16(vdst + row * 144 + ch * 16,
                     VH + ((size_t)(b * 256 + h * 32 + row)) * NTOK + kb + ch * 8);
            }
            CP_COMMIT();
            CP_WAIT1();
        } else {
            CP_WAIT0();
        }
        __syncthreads();
        int st = kt & 1;
        u32 sKst = sKa + st * 5120;
        u32 sVst = sVa + st * 5760;

        float S[2][8][4];
#pragma unroll
        for (int m = 0; m < 2; m++)
#pragma unroll
            for (int n = 0; n < 8; n++)
#pragma unroll
                for (int c = 0; c < 4; c++) S[m][n][c] = 0.f;

#pragma unroll
        for (int ks = 0; ks < 2; ks++) {
            int cb0 = ks * 16;
#pragma unroll
            for (int p = 0; p < 4; p++) {
                u32 t[4];
                int row = p * 16 + ((lane >> 4) & 1) * 8 + (lane & 7);
                int col = cb0 + ((lane >> 3) & 1) * 8;
                ldsm4(t, sKst + row * 80 + col * 2);
                mma16816(S[0][2 * p],     qa[0][ks][0], qa[0][ks][1], qa[0][ks][2], qa[0][ks][3], t[0], t[1]);
                mma16816(S[1][2 * p],     qa[1][ks][0], qa[1][ks][1], qa[1][ks][2], qa[1][ks][3], t[0], t[1]);
                mma16816(S[0][2 * p + 1], qa[0][ks][0], qa[0][ks][1], qa[0][ks][2], qa[0][ks][3], t[2], t[3]);
                mma16816(S[1][2 * p + 1], qa[1][ks][0], qa[1][ks][1], qa[1][ks][2], qa[1][ks][3], t[2], t[3]);
            }
        }

        u32 P[2][8][2];
#pragma unroll
        for (int m = 0; m < 2; m++)
#pragma unroll
            for (int nb = 0; nb < 8; nb++) {
                P[m][nb][0] = ex2h2(f16pack(S[m][nb][0], S[m][nb][1]));
                P[m][nb][1] = ex2h2(f16pack(S[m][nb][2], S[m][nb][3]));
            }

#pragma unroll
        for (int ks = 0; ks < 4; ks++) {
            int cb0 = ks * 16;
#pragma unroll
            for (int p = 0; p < 2; p++) {
                u32 t[4];
                int row = p * 16 + ((lane >> 4) & 1) * 8 + (lane & 7);
                int col = cb0 + ((lane >> 3) & 1) * 8;
                ldsm4(t, sVst + row * 144 + col * 2);
#pragma unroll
                for (int m = 0; m < 2; m++) {
                    mma16816(Oa[m][2 * p],     P[m][2 * ks][0], P[m][2 * ks][1],
                             P[m][2 * ks + 1][0], P[m][2 * ks + 1][1], t[0], t[1]);
                    mma16816(Oa[m][2 * p + 1], P[m][2 * ks][0], P[m][2 * ks][1],
                             P[m][2 * ks + 1][0], P[m][2 * ks + 1][1], t[2], t[3]);
                }
            }
            {
                u32 t2[2];
                int row = 32 + (lane & 7);
                int col = cb0 + ((lane >> 3) & 1) * 8;
                ldsm2(t2, sVst + row * 144 + col * 2);
#pragma unroll
                for (int m = 0; m < 2; m++)
                    mma16816(Oa[m][4], P[m][2 * ks][0], P[m][2 * ks][1],
                             P[m][2 * ks + 1][0], P[m][2 * ks + 1][1], t2[0], t2[1]);
            }
        }
        __syncthreads();
    }

    int qb = q0 + wid * 32;
#pragma unroll
    for (int m = 0; m < 2; m++) {
        float li0 = 1.f / __shfl_sync(0xffffffffu, Oa[m][4][0], lane & ~3);
        float li1 = 1.f / __shfl_sync(0xffffffffu, Oa[m][4][2], lane & ~3);
        int r0 = qb + m * 16 + (lane >> 2);
#pragma unroll
        for (int nb = 0; nb < 4; nb++) {
            int d = nb * 8 + (lane & 3) * 2;
            *(u32*)(OH + ((size_t)b * NTOK + r0) * 256 + h * 32 + d) =
                f16pack(Oa[m][nb][0] * li0, Oa[m][nb][1] * li0);
            *(u32*)(OH + ((size_t)b * NTOK + r0 + 8) * 256 + h * 32 + d) =
                f16pack(Oa[m][nb][2] * li1, Oa[m][nb][3] * li1);
        }
    }
}

// ================= BN =================
__global__ void bnstats_kernel(const float* __restrict__ pre,
                               const float* __restrict__ gamma,
                               const float* __restrict__ beta) {
    int c = blockIdx.x;
    float s = 0.f, s2 = 0.f;
    for (int b = 0; b < 4; b++) {
        const float* p = pre + ((size_t)b * FEATC + c) * NTOK;
        for (int i = threadIdx.x; i < NTOK / 4; i += 256) {
            float4 v = ((const float4*)p)[i];
            s += v.x + v.y + v.z + v.w;
            s2 += v.x * v.x + v.y * v.y + v.z * v.z + v.w * v.w;
        }
    }
    __shared__ float sh0[256], sh1[256];
    sh0[threadIdx.x] = s;
    sh1[threadIdx.x] = s2;
    __syncthreads();
    for (int st = 128; st > 0; st >>= 1) {
        if (threadIdx.x < st) {
            sh0[threadIdx.x] += sh0[threadIdx.x + st];
            sh1[threadIdx.x] += sh1[threadIdx.x + st];
        }
        __syncthreads();
    }
    if (threadIdx.x == 0) {
        const float n = 4.0f * NTOK;
        float mean = sh0[0] / n;
        float var = sh1[0] / n - mean * mean;
        float is = rsqrtf(var + 1e-5f);
        float scl = gamma[c] * is;
        g_scale[c] = scl;
        g_shift[c] = beta[c] - mean * scl;
    }
}

__global__ void bnapply_kernel(const float* __restrict__ pre, float* __restrict__ out) {
    int idx = blockIdx.x * 256 + threadIdx.x;
    if (idx >= 589824) return;
    int c = ((idx << 2) / NTOK) & 255;
    float sc = g_scale[c], sh = g_shift[c];
    float4 v = ((const float4*)pre)[idx];
    v.x = v.x * sc + sh; v.y = v.y * sc + sh;
    v.z = v.z * sc + sh; v.w = v.w * sc + sh;
    ((float4*)out)[idx] = v;
}

// ================= launch =================
extern "C" void kernel_launch(void* const* d_in, const int* in_sizes, int n_in,
                              void* d_out, int out_size) {
    const float* q     = (const float*)d_in[0];
    const float* k     = (const float*)d_in[1];
    const float* v     = (const float*)d_in[2];
    const float* wq    = (const float*)d_in[3];
    const float* wk    = (const float*)d_in[4];
    const float* wv    = (const float*)d_in[5];
    const float* wfc   = (const float*)d_in[6];
    const float* w1    = (const float*)d_in[7];
    const float* b1    = (const float*)d_in[8];
    const float* w2    = (const float*)d_in[9];
    const float* b2    = (const float*)d_in[10];
    const float* gamma = (const float*)d_in[11];
    const float* beta  = (const float*)d_in[12];
    float* out = (float*)d_out;

    float* base = nullptr;
    cudaGetSymbolAddress((void**)&base, g_scratch);
    float* O2  = base;
    float* PRE = base + 2359296;
    __half* hb  = (__half*)(base + 4718592);
    __half* W16 = hb;
    __half* XIN = hb + 409600;
    __half* QH  = hb + 8077312;
    __half* KH  = QH + 2359296;
    __half* VH  = KH + 2359296;
    __half* OH  = VH + 2359296;
    __half* O2h = OH + 2359296;
    __half* H1h = O2h + 2359296;

    pe16_kernel<<<(32 * NTOK + 255) / 256, 256>>>(XIN);
    wconv_kernel<<<1600, 256>>>(wq, wk, wv, wfc, w1, w2, W16);
    {
        dim3 g(NTOK / 128, FEATC / 32, 12);
        xconv_kernel<<<g, 256>>>(q, k, v, XIN);
    }
    {
        dim3 g(NTOK / 128, 2, 12);
        proj_h_kernel<<<g, 256>>>(W16, XIN, QH, KH, VH);
    }
    {
        dim3 ga(NQT, 32);
        attn_mma_kernel<<<ga, 128>>>(QH, KH, VH, OH);
    }
    {
        dim3 g(NTOK / 128, 2, 4);
        hgemm_kernel<<<g, 256>>>(W16 + 212992, OH, nullptr, nullptr, O2, O2h, 0);
        hgemm_kernel<<<g, 256>>>(W16 + 278528, O2h, b1, nullptr, nullptr, H1h, 1);
        hgemm_kernel<<<g, 256>>>(W16 + 344064, H1h, b2, O2, PRE, nullptr, 0);
    }
    bnstats_kernel<<<256, 256>>>(PRE, gamma, beta);
    bnapply_kernel<<<(589824 + 255) / 256, 256>>>(PRE, out);
}